// round 9
// baseline (speedup 1.0000x reference)
#include <cuda_runtime.h>
#include <cuda_bf16.h>
#include <math.h>
#include <stdint.h>
#include <string.h>

#define BQ 16
#define SEQ 1024
#define RDIM 1024
#define NHID 1024
#define HEADS 8
#define DKH 128

// ======================= static scratch ==========================================
__device__ __nv_bfloat16 g_inqh[(size_t)BQ * SEQ * RDIM], g_inql[(size_t)BQ * SEQ * RDIM];
__device__ __nv_bfloat16 g_inkh[(size_t)BQ * SEQ * RDIM], g_inkl[(size_t)BQ * SEQ * RDIM];
__device__ __nv_bfloat16 g_invh[(size_t)BQ * SEQ * RDIM], g_invl[(size_t)BQ * SEQ * RDIM];
__device__ __nv_bfloat16 g_wqh[(size_t)NHID * RDIM], g_wql[(size_t)NHID * RDIM];
__device__ __nv_bfloat16 g_wkh[(size_t)NHID * RDIM], g_wkl[(size_t)NHID * RDIM];
__device__ __nv_bfloat16 g_wvh[(size_t)NHID * RDIM], g_wvl[(size_t)NHID * RDIM];
__device__ __nv_bfloat16 g_wmh[(size_t)NHID * NHID], g_wml[(size_t)NHID * NHID];
__device__ __nv_bfloat16 g_qh[(size_t)BQ * SEQ * NHID], g_ql[(size_t)BQ * SEQ * NHID];
__device__ __nv_bfloat16 g_kh[(size_t)BQ * SEQ * NHID], g_kl[(size_t)BQ * SEQ * NHID];
__device__ __nv_bfloat16 g_vh[(size_t)BQ * SEQ * NHID], g_vl[(size_t)BQ * SEQ * NHID];
__device__ __nv_bfloat16 g_vth[(size_t)BQ * SEQ * NHID], g_vtl[(size_t)BQ * SEQ * NHID];
__device__ __nv_bfloat16 g_aedh[(size_t)BQ * SEQ * NHID], g_aedl[(size_t)BQ * SEQ * NHID];
__device__ float g_attf[(size_t)BQ * HEADS * SEQ * SEQ]; // fallback if att not in d_out
__device__ float g_z[(size_t)BQ * HEADS * SEQ];           // per-row sum of exp
__device__ unsigned char g_mask[(size_t)BQ * SEQ];
__device__ int g_mask_mode;

// ======================= small helpers ===========================================
__device__ __forceinline__ uint32_t s2u(const void* p) {
    uint32_t a;
    asm("{ .reg .u64 t; cvta.to.shared.u64 t, %1; cvt.u32.u64 %0, t; }" : "=r"(a) : "l"(p));
    return a;
}
__device__ __forceinline__ void f2hl(float x, __nv_bfloat16& h, __nv_bfloat16& l) {
    h = __float2bfloat16(x);
    l = __float2bfloat16(x - __bfloat162float(h));
}
__device__ __forceinline__ uint32_t pk2(__nv_bfloat16 a, __nv_bfloat16 b) {
    __nv_bfloat162 t; t.x = a; t.y = b;
    uint32_t u; memcpy(&u, &t, 4);
    return u;
}
__device__ __forceinline__ void cpa16(uint32_t s, const void* g) {
    asm volatile("cp.async.cg.shared.global [%0], [%1], 16;" :: "r"(s), "l"(g) : "memory");
}
__device__ __forceinline__ void ldm_x4(uint32_t r[4], uint32_t addr) {
    asm volatile("ldmatrix.sync.aligned.m8n8.x4.shared.b16 {%0,%1,%2,%3}, [%4];"
                 : "=r"(r[0]), "=r"(r[1]), "=r"(r[2]), "=r"(r[3]) : "r"(addr));
}
__device__ __forceinline__ void mma_bf16(float* c, const uint32_t* a, uint32_t b0, uint32_t b1) {
    asm volatile(
        "mma.sync.aligned.m16n8k16.row.col.f32.bf16.bf16.f32 "
        "{%0,%1,%2,%3}, {%4,%5,%6,%7}, {%8,%9}, {%0,%1,%2,%3};"
        : "+f"(c[0]), "+f"(c[1]), "+f"(c[2]), "+f"(c[3])
        : "r"(a[0]), "r"(a[1]), "r"(a[2]), "r"(a[3]), "r"(b0), "r"(b1));
}
__device__ __forceinline__ void lds128f(float4& v, uint32_t a) {
    asm volatile("ld.shared.v4.f32 {%0,%1,%2,%3}, [%4];"
                 : "=f"(v.x), "=f"(v.y), "=f"(v.z), "=f"(v.w) : "r"(a));
}
__device__ __forceinline__ void sts128(uint32_t a, uint32_t x0, uint32_t x1, uint32_t x2, uint32_t x3) {
    asm volatile("st.shared.v4.b32 [%0], {%1,%2,%3,%4};"
                 :: "r"(a), "r"(x0), "r"(x1), "r"(x2), "r"(x3) : "memory");
}

#define STAGE_BYTES 65536
#define NSTAGE 3
#define GEMM_SMEM (NSTAGE * STAGE_BYTES)   // 196608
#define PV_STAGE 98304
#define PV_SMEM (2 * PV_STAGE)             // 196608

// ======================= mask canonicalization ===================================
__global__ void detect_mask_mode(const unsigned int* __restrict__ m) {
    __shared__ int s_non01f, s_f32w;
    if (threadIdx.x == 0) { s_non01f = 0; s_f32w = 0; }
    __syncthreads();
    int ln = 0, lf = 0;
    for (int i = threadIdx.x; i < 4096; i += blockDim.x) {
        unsigned int w = m[i];
        if (w == 0x3F800000u) lf = 1;
        else if (w > 1u) ln = 1;
    }
    if (ln) atomicOr(&s_non01f, 1);
    if (lf) atomicOr(&s_f32w, 1);
    __syncthreads();
    if (threadIdx.x == 0) {
        if (s_non01f) g_mask_mode = 0;
        else if (s_f32w) g_mask_mode = 2;
        else g_mask_mode = 1;
    }
}
__global__ void convert_mask(const void* __restrict__ m, unsigned char* __restrict__ outm, int n) {
    int i = blockIdx.x * blockDim.x + threadIdx.x;
    if (i >= n) return;
    int mode = g_mask_mode;
    unsigned char r;
    if (mode == 0)      r = ((const unsigned char*)m)[i] ? 1 : 0;
    else if (mode == 1) r = ((const int*)m)[i] ? 1 : 0;
    else                r = (((const float*)m)[i] != 0.0f) ? 1 : 0;
    outm[i] = r;
}

__global__ void zero_z(float* __restrict__ z, int n) {
    int i = blockIdx.x * blockDim.x + threadIdx.x;
    if (i < n) z[i] = 0.f;
}

// ======================= conversions (fused) =====================================
__global__ void conv_all(const float* __restrict__ q, const float* __restrict__ k,
                         const float* __restrict__ v,
                         __nv_bfloat16* __restrict__ qh, __nv_bfloat16* __restrict__ ql,
                         __nv_bfloat16* __restrict__ kh, __nv_bfloat16* __restrict__ kl,
                         __nv_bfloat16* __restrict__ vh, __nv_bfloat16* __restrict__ vl,
                         int n4) {
    int i = blockIdx.x * blockDim.x + threadIdx.x;
    if (i >= n4) return;
    int sel = blockIdx.y;
    const float* s = (sel == 0) ? q : (sel == 1) ? k : v;
    __nv_bfloat16* h = (sel == 0) ? qh : (sel == 1) ? kh : vh;
    __nv_bfloat16* l = (sel == 0) ? ql : (sel == 1) ? kl : vl;
    float4 vv = ((const float4*)s)[i];
    __nv_bfloat16 h0, l0, h1, l1, h2, l2, h3, l3;
    f2hl(vv.x, h0, l0); f2hl(vv.y, h1, l1); f2hl(vv.z, h2, l2); f2hl(vv.w, h3, l3);
    __nv_bfloat162 a, b, c, d;
    a.x = h0; a.y = h1; b.x = h2; b.y = h3;
    c.x = l0; c.y = l1; d.x = l2; d.y = l3;
    ((__nv_bfloat162*)h)[i * 2] = a;
    ((__nv_bfloat162*)h)[i * 2 + 1] = b;
    ((__nv_bfloat162*)l)[i * 2] = c;
    ((__nv_bfloat162*)l)[i * 2 + 1] = d;
}

// W [K,N] f32 -> Wt [N,K] hi/lo bf16, 4 weights fused (blockIdx.z selects)
__global__ void transW_all(const float* __restrict__ W0, const float* __restrict__ W1,
                           const float* __restrict__ W2, const float* __restrict__ W3,
                           __nv_bfloat16* __restrict__ h0p, __nv_bfloat16* __restrict__ l0p,
                           __nv_bfloat16* __restrict__ h1p, __nv_bfloat16* __restrict__ l1p,
                           __nv_bfloat16* __restrict__ h2p, __nv_bfloat16* __restrict__ l2p,
                           __nv_bfloat16* __restrict__ h3p, __nv_bfloat16* __restrict__ l3p) {
    int s = blockIdx.z;
    const float* W = (s == 0) ? W0 : (s == 1) ? W1 : (s == 2) ? W2 : W3;
    __nv_bfloat16* th = (s == 0) ? h0p : (s == 1) ? h1p : (s == 2) ? h2p : h3p;
    __nv_bfloat16* tl = (s == 0) ? l0p : (s == 1) ? l1p : (s == 2) ? l2p : l3p;
    __shared__ float tile[32][33];
    int n = blockIdx.x * 32 + threadIdx.x;
    int k0 = blockIdx.y * 32;
    for (int i = threadIdx.y; i < 32; i += 8)
        tile[i][threadIdx.x] = W[(long long)(k0 + i) * NHID + n];
    __syncthreads();
    int k = k0 + threadIdx.x;
    int nr0 = blockIdx.x * 32;
    for (int i = threadIdx.y; i < 32; i += 8) {
        float f = tile[threadIdx.x][i];
        __nv_bfloat16 h, l;
        f2hl(f, h, l);
        th[(long long)(nr0 + i) * RDIM + k] = h;
        tl[(long long)(nr0 + i) * RDIM + k] = l;
    }
}

// v [b, t, c] bf16 -> vT [b, c, t]  (per-b 1024x1024 transpose, hi and lo)
__global__ void transV(const __nv_bfloat16* __restrict__ vh, const __nv_bfloat16* __restrict__ vl,
                       __nv_bfloat16* __restrict__ oh, __nv_bfloat16* __restrict__ ol) {
    int b = blockIdx.z;
    __shared__ __nv_bfloat16 th[32][33], tl2[32][33];
    long long base = (long long)b * SEQ * NHID;
    int c = blockIdx.x * 32 + threadIdx.x;
    int t0 = blockIdx.y * 32;
    for (int i = threadIdx.y; i < 32; i += 8) {
        th[i][threadIdx.x] = vh[base + (long long)(t0 + i) * NHID + c];
        tl2[i][threadIdx.x] = vl[base + (long long)(t0 + i) * NHID + c];
    }
    __syncthreads();
    int t = t0 + threadIdx.x;
    int c0 = blockIdx.x * 32;
    for (int i = threadIdx.y; i < 32; i += 8) {
        oh[base + (long long)(c0 + i) * SEQ + t] = th[threadIdx.x][i];
        ol[base + (long long)(c0 + i) * SEQ + t] = tl2[threadIdx.x][i];
    }
}

// ======================= shared GEMM building blocks =============================
__device__ __forceinline__ void load_mat(uint32_t sBase, const __nv_bfloat16* g, int ld, int kt, int tid) {
#pragma unroll
    for (int i = 0; i < 4; i++) {
        int u = tid + (i << 8);
        int r = u >> 3, cu = u & 7;
        uint32_t off = (uint32_t)(r * 128 + cu * 16);
        off ^= (off >> 3) & 0x70;
        cpa16(sBase + off, g + (long long)r * ld + kt + (cu << 3));
    }
}

__device__ __forceinline__ uint32_t swadr(uint32_t base, int row, int bcol) {
    return base + (uint32_t)(row * 128) + (uint32_t)(bcol ^ ((row & 7) << 4));
}

#define LOADFRAGS(buf, kb) do {                                             \
    _Pragma("unroll")                                                       \
    for (int mi = 0; mi < 2; mi++) {                                        \
        int r_ = wm * 32 + mi * 16 + aRow;                                  \
        ldm_x4(ahf[buf][mi], swadr(aBh, r_, (kb) + aColB));                 \
        ldm_x4(alf[buf][mi], swadr(aBl, r_, (kb) + aColB));                 \
    }                                                                       \
    _Pragma("unroll")                                                       \
    for (int j = 0; j < 4; j++) {                                           \
        int rn_ = wn * 64 + j * 16 + bRow;                                  \
        ldm_x4(bhf[buf][j], swadr(bBh, rn_, (kb) + bColB));                 \
        ldm_x4(blf[buf][j], swadr(bBl, rn_, (kb) + bColB));                 \
    }                                                                       \
} while (0)

#define DOMMAS(buf) do {                                                    \
    _Pragma("unroll")                                                       \
    for (int mi = 0; mi < 2; mi++)                                          \
        _Pragma("unroll")                                                   \
        for (int j = 0; j < 4; j++)                                         \
            _Pragma("unroll")                                               \
            for (int nn = 0; nn < 2; nn++)                                  \
                mma_bf16(acc[mi][2 * j + nn], ahf[buf][mi],                 \
                         bhf[buf][j][nn * 2], bhf[buf][j][nn * 2 + 1]);     \
    _Pragma("unroll")                                                       \
    for (int mi = 0; mi < 2; mi++)                                          \
        _Pragma("unroll")                                                   \
        for (int j = 0; j < 4; j++)                                         \
            _Pragma("unroll")                                               \
            for (int nn = 0; nn < 2; nn++)                                  \
                mma_bf16(acc[mi][2 * j + nn], ahf[buf][mi],                 \
                         blf[buf][j][nn * 2], blf[buf][j][nn * 2 + 1]);     \
    _Pragma("unroll")                                                       \
    for (int mi = 0; mi < 2; mi++)                                          \
        _Pragma("unroll")                                                   \
        for (int j = 0; j < 4; j++)                                         \
            _Pragma("unroll")                                               \
            for (int nn = 0; nn < 2; nn++)                                  \
                mma_bf16(acc[mi][2 * j + nn], alf[buf][mi],                 \
                         bhf[buf][j][nn * 2], bhf[buf][j][nn * 2 + 1]);     \
} while (0)

// ======================= HMMA bf16x3 GEMM ========================================
// EPI: 0 = hi/lo bf16 out (+opt bias), 1 = f32 out (+bias),
//      2 = scores: write exp(scale*s) (masked->0), atomicAdd row sums into Zbuf.
__device__ __forceinline__ void load_chunk(uint32_t stage,
                                           const __nv_bfloat16* Azh, const __nv_bfloat16* Azl, int lda,
                                           const __nv_bfloat16* Bzh, const __nv_bfloat16* Bzl, int ldb,
                                           int kt, int tid) {
    load_mat(stage,         Azh, lda, kt, tid);
    load_mat(stage + 16384, Azl, lda, kt, tid);
    load_mat(stage + 32768, Bzh, ldb, kt, tid);
    load_mat(stage + 49152, Bzl, ldb, kt, tid);
    asm volatile("cp.async.commit_group;" ::: "memory");
}

template <int EPI>
__global__ void __launch_bounds__(256) gemm3(
    const __nv_bfloat16* __restrict__ Ah, const __nv_bfloat16* __restrict__ Al,
    int lda, long long sA1, long long sA2,
    const __nv_bfloat16* __restrict__ Bh, const __nv_bfloat16* __restrict__ Bl,
    int ldb, long long sB1, long long sB2,
    const float* __restrict__ bias,
    float* __restrict__ Cf, __nv_bfloat16* __restrict__ Ch, __nv_bfloat16* __restrict__ Cl,
    int ldc, long long sC1, long long sC2,
    int Ktot, const unsigned char* __restrict__ mask, float scale,
    float* __restrict__ Zbuf)
{
    extern __shared__ char smem[];
    uint32_t sb = s2u(smem);
    int tid = threadIdx.x;
    int wid = tid >> 5, lane = tid & 31;
    int wm = wid & 3, wn = wid >> 2;

    int z = blockIdx.z;
    int zb = z / HEADS, zh = z % HEADS;
    int m0 = blockIdx.y * 128, n0 = blockIdx.x * 128;
    const __nv_bfloat16* Azh = Ah + zb * sA1 + zh * sA2 + (long long)m0 * lda;
    const __nv_bfloat16* Azl = Al + zb * sA1 + zh * sA2 + (long long)m0 * lda;
    const __nv_bfloat16* Bzh = Bh + zb * sB1 + zh * sB2 + (long long)n0 * ldb;
    const __nv_bfloat16* Bzl = Bl + zb * sB1 + zh * sB2 + (long long)n0 * ldb;

    float acc[2][8][4];
#pragma unroll
    for (int i = 0; i < 2; i++)
#pragma unroll
        for (int j = 0; j < 8; j++)
#pragma unroll
            for (int q = 0; q < 4; q++) acc[i][j][q] = 0.f;

    int nch = Ktot >> 6;

    load_chunk(sb, Azh, Azl, lda, Bzh, Bzl, ldb, 0, tid);
    if (nch > 1)
        load_chunk(sb + STAGE_BYTES, Azh, Azl, lda, Bzh, Bzl, ldb, 64, tid);

    int aRow = (lane & 15);
    int aColB = (lane >> 4) << 4;
    int bRow = (lane & 7) + ((lane >> 4) << 3);
    int bColB = ((lane >> 3) & 1) << 4;

    uint32_t ahf[2][2][4], alf[2][2][4], bhf[2][4][4], blf[2][4][4];

    for (int c = 0; c < nch; c++) {
        if (c < nch - 1) {
            asm volatile("cp.async.wait_group 1;" ::: "memory");
        } else {
            asm volatile("cp.async.wait_group 0;" ::: "memory");
        }
        __syncthreads();

        if (c + 2 < nch)
            load_chunk(sb + ((c + 2) % NSTAGE) * STAGE_BYTES,
                       Azh, Azl, lda, Bzh, Bzl, ldb, (c + 2) << 6, tid);

        uint32_t bp = sb + (c % NSTAGE) * STAGE_BYTES;
        uint32_t aBh = bp, aBl = bp + 16384, bBh = bp + 32768, bBl = bp + 49152;

        LOADFRAGS(0, 0);
#pragma unroll
        for (int ks = 0; ks < 4; ks++) {
            if (ks < 3) LOADFRAGS((ks + 1) & 1, (ks + 1) << 5);
            DOMMAS(ks & 1);
        }
    }

    // ---------------- epilogue -----------------
    int gm = m0 + wm * 32;
    int gn = n0 + wn * 64;
    long long cbase = zb * sC1 + zh * sC2;

#pragma unroll
    for (int mi = 0; mi < 2; mi++) {
#pragma unroll
        for (int half = 0; half < 2; half++) {
            int r = gm + mi * 16 + half * 8 + (lane >> 2);
            float rowsum = 0.f;
#pragma unroll
            for (int ni = 0; ni < 8; ni++) {
                int cc = gn + ni * 8 + (lane & 3) * 2;
                float f0 = acc[mi][ni][half * 2 + 0];
                float f1 = acc[mi][ni][half * 2 + 1];
                if (EPI == 0) {
                    if (bias) { f0 += bias[cc]; f1 += bias[cc + 1]; }
                    __nv_bfloat16 h0, l0, h1, l1;
                    f2hl(f0, h0, l0); f2hl(f1, h1, l1);
                    __nv_bfloat162 vh2, vl2;
                    vh2.x = h0; vh2.y = h1; vl2.x = l0; vl2.y = l1;
                    *(__nv_bfloat162*)(Ch + cbase + (long long)r * ldc + cc) = vh2;
                    *(__nv_bfloat162*)(Cl + cbase + (long long)r * ldc + cc) = vl2;
                } else if (EPI == 1) {
                    float2 v;
                    v.x = f0 + bias[cc];
                    v.y = f1 + bias[cc + 1];
                    *(float2*)(Cf + cbase + (long long)r * ldc + cc) = v;
                } else {
                    const unsigned char* mb = mask + (long long)zb * SEQ;
                    float e0 = mb[cc]     ? 0.f : expf(f0 * scale);
                    float e1 = mb[cc + 1] ? 0.f : expf(f1 * scale);
                    float2 v; v.x = e0; v.y = e1;
                    *(float2*)(Cf + cbase + (long long)r * ldc + cc) = v;
                    rowsum += e0 + e1;
                }
            }
            if (EPI == 2) {
                rowsum += __shfl_xor_sync(0xffffffffu, rowsum, 1);
                rowsum += __shfl_xor_sync(0xffffffffu, rowsum, 2);
                if ((lane & 3) == 0)
                    atomicAdd(&Zbuf[(long long)z * SEQ + r], rowsum);
            }
        }
    }
}

// ======================= PV GEMM (exp f32 A, normalize + write att) ==============
// Reads exp values, multiplies by 1/Z, writes normalized att back to global,
// converts normalized p to hi/lo bf16 in SMEM, GEMM against V^T.
__device__ __forceinline__ void load_pv_chunk(uint32_t stage,
                                              const float* Af, int lda,
                                              const __nv_bfloat16* Bzh, const __nv_bfloat16* Bzl, int ldb,
                                              int kt, int tid) {
#pragma unroll
    for (int i = 0; i < 8; i++) {
        int gid = tid + (i << 8);
        int r = gid >> 4, cu = gid & 15;
        cpa16(stage + (uint32_t)(r * 256 + cu * 16), Af + (long long)r * lda + kt + (cu << 2));
    }
    load_mat(stage + 65536, Bzh, ldb, kt, tid);
    load_mat(stage + 81920, Bzl, ldb, kt, tid);
    asm volatile("cp.async.commit_group;" ::: "memory");
}

__global__ void __launch_bounds__(256) gemm_pv(
    float* __restrict__ Att, const float* __restrict__ Zbuf,
    const __nv_bfloat16* __restrict__ Vth, const __nv_bfloat16* __restrict__ Vtl,
    __nv_bfloat16* __restrict__ Ch, __nv_bfloat16* __restrict__ Cl)
{
    extern __shared__ char smem[];
    uint32_t sb = s2u(smem);
    int tid = threadIdx.x;
    int wid = tid >> 5, lane = tid & 31;
    int wm = wid & 3, wn = wid >> 2;

    int z = blockIdx.z;
    int zb = z / HEADS, zh = z % HEADS;
    int m0 = blockIdx.y * 128;
    float* Af = Att + (long long)z * SEQ * SEQ + (long long)m0 * SEQ;
    const __nv_bfloat16* Bzh = Vth + (long long)zb * SEQ * NHID + (long long)zh * DKH * SEQ;
    const __nv_bfloat16* Bzl = Vtl + (long long)zb * SEQ * NHID + (long long)zh * DKH * SEQ;

    float acc[2][8][4];
#pragma unroll
    for (int i = 0; i < 2; i++)
#pragma unroll
        for (int j = 0; j < 8; j++)
#pragma unroll
            for (int q = 0; q < 4; q++) acc[i][j][q] = 0.f;

    const int nch = SEQ >> 6;  // 16

    load_pv_chunk(sb, Af, SEQ, Bzh, Bzl, SEQ, 0, tid);

    int aRow = (lane & 15);
    int aColB = (lane >> 4) << 4;
    int bRow = (lane & 7) + ((lane >> 4) << 3);
    int bColB = ((lane >> 3) & 1) << 4;

    uint32_t ahf[2][2][4], alf[2][2][4], bhf[2][4][4], blf[2][4][4];

    for (int c = 0; c < nch; c++) {
        asm volatile("cp.async.wait_group 0;" ::: "memory");
        __syncthreads();

        uint32_t stage = sb + (uint32_t)(c & 1) * PV_STAGE;
        int kt = c << 6;

        // prefetch next chunk into the other stage (disjoint att cols -> no race)
        if (c + 1 < nch)
            load_pv_chunk(sb + (uint32_t)((c + 1) & 1) * PV_STAGE,
                          Af, SEQ, Bzh, Bzl, SEQ, (c + 1) << 6, tid);

        // normalize (1/Z), write att back, convert to hi/lo bf16 swizzled tiles
#pragma unroll
        for (int i = 0; i < 4; i++) {
            int gid = tid + (i << 8);
            int r = gid >> 3, cu = gid & 7;
            uint32_t src = stage + (uint32_t)(r * 256 + cu * 32);
            float4 v0, v1;
            lds128f(v0, src);
            lds128f(v1, src + 16);
            float invZ = 1.f / Zbuf[(long long)z * SEQ + m0 + r];
            v0.x *= invZ; v0.y *= invZ; v0.z *= invZ; v0.w *= invZ;
            v1.x *= invZ; v1.y *= invZ; v1.z *= invZ; v1.w *= invZ;
            float* gout = Af + (long long)r * SEQ + kt + cu * 8;
            *(float4*)gout = v0;
            *(float4*)(gout + 4) = v1;
            __nv_bfloat16 h0, l0, h1, l1, h2, l2, h3, l3, h4, l4, h5, l5, h6, l6, h7, l7;
            f2hl(v0.x, h0, l0); f2hl(v0.y, h1, l1); f2hl(v0.z, h2, l2); f2hl(v0.w, h3, l3);
            f2hl(v1.x, h4, l4); f2hl(v1.y, h5, l5); f2hl(v1.z, h6, l6); f2hl(v1.w, h7, l7);
            uint32_t off = (uint32_t)(r * 128 + cu * 16);
            off ^= (off >> 3) & 0x70;
            sts128(stage + 32768 + off, pk2(h0, h1), pk2(h2, h3), pk2(h4, h5), pk2(h6, h7));
            sts128(stage + 49152 + off, pk2(l0, l1), pk2(l2, l3), pk2(l4, l5), pk2(l6, l7));
        }
        __syncthreads();

        uint32_t aBh = stage + 32768, aBl = stage + 49152;
        uint32_t bBh = stage + 65536, bBl = stage + 81920;

        LOADFRAGS(0, 0);
#pragma unroll
        for (int ks = 0; ks < 4; ks++) {
            if (ks < 3) LOADFRAGS((ks + 1) & 1, (ks + 1) << 5);
            DOMMAS(ks & 1);
        }
    }

    // epilogue: hi/lo bf16 out, no bias. C row stride NHID, head offset zh*DKH.
    int gm = m0 + wm * 32;
    int gn = wn * 64;
    long long cbase = (long long)zb * SEQ * NHID + (long long)zh * DKH;

#pragma unroll
    for (int mi = 0; mi < 2; mi++) {
#pragma unroll
        for (int half = 0; half < 2; half++) {
            int r = gm + mi * 16 + half * 8 + (lane >> 2);
#pragma unroll
            for (int ni = 0; ni < 8; ni++) {
                int cc = gn + ni * 8 + (lane & 3) * 2;
                float f0 = acc[mi][ni][half * 2 + 0];
                float f1 = acc[mi][ni][half * 2 + 1];
                __nv_bfloat16 h0, l0, h1, l1;
                f2hl(f0, h0, l0); f2hl(f1, h1, l1);
                __nv_bfloat162 vh2, vl2;
                vh2.x = h0; vh2.y = h1; vl2.x = l0; vl2.y = l1;
                *(__nv_bfloat162*)(Ch + cbase + (long long)r * NHID + cc) = vh2;
                *(__nv_bfloat162*)(Cl + cbase + (long long)r * NHID + cc) = vl2;
            }
        }
    }
}

// ======================= host ====================================================
extern "C" void kernel_launch(void* const* d_in, const int* in_sizes, int n_in,
                              void* d_out, int out_size)
{
    const float* v_in  = (const float*)d_in[0];
    const float* key   = (const float*)d_in[1];
    const float* query = (const float*)d_in[2];
    const void*  mask  = d_in[3];
    const float* Wq = (const float*)d_in[4];
    const float* bq = (const float*)d_in[5];
    const float* Wk = (const float*)d_in[6];
    const float* bk = (const float*)d_in[7];
    const float* Wv = (const float*)d_in[8];
    const float* bv = (const float*)d_in[9];
    const float* Wm = (const float*)d_in[10];
    const float* bm = (const float*)d_in[11];
    float* out = (float*)d_out;

    const long long ATTED_N = (long long)BQ * SEQ * NHID;
    const long long ATT_N   = (long long)BQ * HEADS * SEQ * SEQ;

#define GETP(sym, ty, var) ty* var; cudaGetSymbolAddress((void**)&var, sym)
    GETP(g_inqh, __nv_bfloat16, inqh); GETP(g_inql, __nv_bfloat16, inql);
    GETP(g_inkh, __nv_bfloat16, inkh); GETP(g_inkl, __nv_bfloat16, inkl);
    GETP(g_invh, __nv_bfloat16, invh); GETP(g_invl, __nv_bfloat16, invl);
    GETP(g_wqh, __nv_bfloat16, wqh); GETP(g_wql, __nv_bfloat16, wql);
    GETP(g_wkh, __nv_bfloat16, wkh); GETP(g_wkl, __nv_bfloat16, wkl);
    GETP(g_wvh, __nv_bfloat16, wvh); GETP(g_wvl, __nv_bfloat16, wvl);
    GETP(g_wmh, __nv_bfloat16, wmh); GETP(g_wml, __nv_bfloat16, wml);
    GETP(g_qh, __nv_bfloat16, qh); GETP(g_ql, __nv_bfloat16, ql);
    GETP(g_kh, __nv_bfloat16, kh); GETP(g_kl, __nv_bfloat16, kl);
    GETP(g_vh, __nv_bfloat16, vh); GETP(g_vl, __nv_bfloat16, vl);
    GETP(g_vth, __nv_bfloat16, vth); GETP(g_vtl, __nv_bfloat16, vtl);
    GETP(g_aedh, __nv_bfloat16, aedh); GETP(g_aedl, __nv_bfloat16, aedl);
    GETP(g_attf, float, attf);
    GETP(g_z, float, zp);
    GETP(g_mask, unsigned char, maskp);
#undef GETP

    float* att_ptr;
    float* atted_ptr = out;
    if ((long long)out_size >= ATTED_N + ATT_N) {
        att_ptr = out + ATTED_N;
    } else {
        att_ptr = attf;
    }

    cudaFuncSetAttribute(gemm3<0>, cudaFuncAttributeMaxDynamicSharedMemorySize, GEMM_SMEM);
    cudaFuncSetAttribute(gemm3<1>, cudaFuncAttributeMaxDynamicSharedMemorySize, GEMM_SMEM);
    cudaFuncSetAttribute(gemm3<2>, cudaFuncAttributeMaxDynamicSharedMemorySize, GEMM_SMEM);
    cudaFuncSetAttribute(gemm_pv, cudaFuncAttributeMaxDynamicSharedMemorySize, PV_SMEM);

    const float scale = 1.0f / sqrtf((float)DKH);
    dim3 blk(256);

    // (0) input conversions (fused q/k/v)
    {
        int n4 = (int)(ATTED_N / 4);
        dim3 g((n4 + 255) / 256, 3);
        conv_all<<<g, 256>>>(query, key, v_in, inqh, inql, inkh, inkl, invh, invl, n4);
    }
    // (1) weight transposes (fused)
    {
        dim3 g(32, 32, 4), b(32, 8);
        transW_all<<<g, b>>>(Wq, Wk, Wv, Wm, wqh, wql, wkh, wkl, wvh, wvl, wmh, wml);
    }

    // (2-4) Projections — placed here so ncu's fixed sample window lands on gemm3
    {
        dim3 grid(NHID / 128, (BQ * SEQ) / 128, 1);
        gemm3<0><<<grid, blk, GEMM_SMEM>>>(inqh, inql, RDIM, 0, 0,
                                           wqh, wql, RDIM, 0, 0, bq,
                                           nullptr, qh, ql, NHID, 0, 0,
                                           RDIM, nullptr, 0.f, nullptr);
        gemm3<0><<<grid, blk, GEMM_SMEM>>>(inkh, inkl, RDIM, 0, 0,
                                           wkh, wkl, RDIM, 0, 0, bk,
                                           nullptr, kh, kl, NHID, 0, 0,
                                           RDIM, nullptr, 0.f, nullptr);
        gemm3<0><<<grid, blk, GEMM_SMEM>>>(invh, invl, RDIM, 0, 0,
                                           wvh, wvl, RDIM, 0, 0, bv,
                                           nullptr, vh, vl, NHID, 0, 0,
                                           RDIM, nullptr, 0.f, nullptr);
    }

    // (5) V transpose per batch
    {
        dim3 g(32, 32, BQ), b(32, 8);
        transV<<<g, b>>>(vh, vl, vth, vtl);
    }

    // (6,7) mask canonicalization; (8) zero Z
    detect_mask_mode<<<1, 256>>>((const unsigned int*)mask);
    convert_mask<<<(BQ * SEQ + 255) / 256, 256>>>(mask, maskp, BQ * SEQ);
    zero_z<<<(BQ * HEADS * SEQ + 255) / 256, 256>>>(zp, BQ * HEADS * SEQ);

    // (9) Scores: write exp(scale*s) masked->0, accumulate row sums
    {
        dim3 grid(SEQ / 128, SEQ / 128, BQ * HEADS);
        gemm3<2><<<grid, blk, GEMM_SMEM>>>(qh, ql, NHID, (long long)SEQ * NHID, DKH,
                                           kh, kl, NHID, (long long)SEQ * NHID, DKH,
                                           nullptr,
                                           att_ptr, nullptr, nullptr, SEQ,
                                           (long long)HEADS * SEQ * SEQ, (long long)SEQ * SEQ,
                                           DKH, maskp, scale, zp);
    }

    // (10) PV: normalize + write att + GEMM against V^T
    {
        dim3 grid(1, SEQ / 128, BQ * HEADS);
        gemm_pv<<<grid, blk, PV_SMEM>>>(att_ptr, zp, vth, vtl, aedh, aedl);
    }

    // (11) Output projection
    {
        dim3 grid(NHID / 128, (BQ * SEQ) / 128, 1);
        gemm3<1><<<grid, blk, GEMM_SMEM>>>(aedh, aedl, NHID, 0, 0,
                                           wmh, wml, NHID, 0, 0, bm,
                                           atted_ptr, nullptr, nullptr, NHID, 0, 0,
                                           NHID, nullptr, 0.f, nullptr);
    }
}

// round 10
// speedup vs baseline: 1.0286x; 1.0286x over previous
#include <cuda_runtime.h>
#include <cuda_bf16.h>
#include <math.h>
#include <stdint.h>
#include <string.h>

#define BQ 16
#define SEQ 1024
#define RDIM 1024
#define NHID 1024
#define HEADS 8
#define DKH 128

// ======================= static scratch ==========================================
__device__ __nv_bfloat16 g_inqh[(size_t)BQ * SEQ * RDIM], g_inql[(size_t)BQ * SEQ * RDIM];
__device__ __nv_bfloat16 g_inkh[(size_t)BQ * SEQ * RDIM], g_inkl[(size_t)BQ * SEQ * RDIM];
__device__ __nv_bfloat16 g_invh[(size_t)BQ * SEQ * RDIM], g_invl[(size_t)BQ * SEQ * RDIM];
__device__ __nv_bfloat16 g_wqh[(size_t)NHID * RDIM], g_wql[(size_t)NHID * RDIM];
__device__ __nv_bfloat16 g_wkh[(size_t)NHID * RDIM], g_wkl[(size_t)NHID * RDIM];
__device__ __nv_bfloat16 g_wvh[(size_t)NHID * RDIM], g_wvl[(size_t)NHID * RDIM];
__device__ __nv_bfloat16 g_wmh[(size_t)NHID * NHID], g_wml[(size_t)NHID * NHID];
__device__ __nv_bfloat16 g_qh[(size_t)BQ * SEQ * NHID], g_ql[(size_t)BQ * SEQ * NHID];
__device__ __nv_bfloat16 g_kh[(size_t)BQ * SEQ * NHID], g_kl[(size_t)BQ * SEQ * NHID];
__device__ __nv_bfloat16 g_vh[(size_t)BQ * SEQ * NHID], g_vl[(size_t)BQ * SEQ * NHID];
__device__ __nv_bfloat16 g_vth[(size_t)BQ * SEQ * NHID], g_vtl[(size_t)BQ * SEQ * NHID];
__device__ __nv_bfloat16 g_aedh[(size_t)BQ * SEQ * NHID], g_aedl[(size_t)BQ * SEQ * NHID];
__device__ float g_attf[(size_t)BQ * HEADS * SEQ * SEQ]; // fallback if att not in d_out
__device__ unsigned char g_mask[(size_t)BQ * SEQ];
__device__ int g_mask_mode;

// ======================= small helpers ===========================================
__device__ __forceinline__ uint32_t s2u(const void* p) {
    uint32_t a;
    asm("{ .reg .u64 t; cvta.to.shared.u64 t, %1; cvt.u32.u64 %0, t; }" : "=r"(a) : "l"(p));
    return a;
}
__device__ __forceinline__ void f2hl(float x, __nv_bfloat16& h, __nv_bfloat16& l) {
    h = __float2bfloat16(x);
    l = __float2bfloat16(x - __bfloat162float(h));
}
__device__ __forceinline__ uint32_t pk2(__nv_bfloat16 a, __nv_bfloat16 b) {
    __nv_bfloat162 t; t.x = a; t.y = b;
    uint32_t u; memcpy(&u, &t, 4);
    return u;
}
__device__ __forceinline__ void cpa16(uint32_t s, const void* g) {
    asm volatile("cp.async.cg.shared.global [%0], [%1], 16;" :: "r"(s), "l"(g) : "memory");
}
__device__ __forceinline__ void ldm_x4(uint32_t r[4], uint32_t addr) {
    asm volatile("ldmatrix.sync.aligned.m8n8.x4.shared.b16 {%0,%1,%2,%3}, [%4];"
                 : "=r"(r[0]), "=r"(r[1]), "=r"(r[2]), "=r"(r[3]) : "r"(addr));
}
__device__ __forceinline__ void mma_bf16(float* c, const uint32_t* a, uint32_t b0, uint32_t b1) {
    asm volatile(
        "mma.sync.aligned.m16n8k16.row.col.f32.bf16.bf16.f32 "
        "{%0,%1,%2,%3}, {%4,%5,%6,%7}, {%8,%9}, {%0,%1,%2,%3};"
        : "+f"(c[0]), "+f"(c[1]), "+f"(c[2]), "+f"(c[3])
        : "r"(a[0]), "r"(a[1]), "r"(a[2]), "r"(a[3]), "r"(b0), "r"(b1));
}
__device__ __forceinline__ void lds128f(float4& v, uint32_t a) {
    asm volatile("ld.shared.v4.f32 {%0,%1,%2,%3}, [%4];"
                 : "=f"(v.x), "=f"(v.y), "=f"(v.z), "=f"(v.w) : "r"(a));
}
__device__ __forceinline__ void sts128(uint32_t a, uint32_t x0, uint32_t x1, uint32_t x2, uint32_t x3) {
    asm volatile("st.shared.v4.b32 [%0], {%1,%2,%3,%4};"
                 :: "r"(a), "r"(x0), "r"(x1), "r"(x2), "r"(x3) : "memory");
}

#define STAGE_BYTES 65536
#define NSTAGE 3
#define GEMM_SMEM (NSTAGE * STAGE_BYTES)   // 196608
#define PV_STAGE 98304
#define PV_SMEM (2 * PV_STAGE)             // 196608

// ======================= mask canonicalization ===================================
__global__ void detect_mask_mode(const unsigned int* __restrict__ m) {
    __shared__ int s_non01f, s_f32w;
    if (threadIdx.x == 0) { s_non01f = 0; s_f32w = 0; }
    __syncthreads();
    int ln = 0, lf = 0;
    for (int i = threadIdx.x; i < 4096; i += blockDim.x) {
        unsigned int w = m[i];
        if (w == 0x3F800000u) lf = 1;
        else if (w > 1u) ln = 1;
    }
    if (ln) atomicOr(&s_non01f, 1);
    if (lf) atomicOr(&s_f32w, 1);
    __syncthreads();
    if (threadIdx.x == 0) {
        if (s_non01f) g_mask_mode = 0;
        else if (s_f32w) g_mask_mode = 2;
        else g_mask_mode = 1;
    }
}
__global__ void convert_mask(const void* __restrict__ m, unsigned char* __restrict__ outm, int n) {
    int i = blockIdx.x * blockDim.x + threadIdx.x;
    if (i >= n) return;
    int mode = g_mask_mode;
    unsigned char r;
    if (mode == 0)      r = ((const unsigned char*)m)[i] ? 1 : 0;
    else if (mode == 1) r = ((const int*)m)[i] ? 1 : 0;
    else                r = (((const float*)m)[i] != 0.0f) ? 1 : 0;
    outm[i] = r;
}

// ======================= conversions (fused) =====================================
__global__ void conv_all(const float* __restrict__ q, const float* __restrict__ k,
                         const float* __restrict__ v,
                         __nv_bfloat16* __restrict__ qh, __nv_bfloat16* __restrict__ ql,
                         __nv_bfloat16* __restrict__ kh, __nv_bfloat16* __restrict__ kl,
                         __nv_bfloat16* __restrict__ vh, __nv_bfloat16* __restrict__ vl,
                         int n4) {
    int i = blockIdx.x * blockDim.x + threadIdx.x;
    if (i >= n4) return;
    int sel = blockIdx.y;
    const float* s = (sel == 0) ? q : (sel == 1) ? k : v;
    __nv_bfloat16* h = (sel == 0) ? qh : (sel == 1) ? kh : vh;
    __nv_bfloat16* l = (sel == 0) ? ql : (sel == 1) ? kl : vl;
    float4 vv = ((const float4*)s)[i];
    __nv_bfloat16 h0, l0, h1, l1, h2, l2, h3, l3;
    f2hl(vv.x, h0, l0); f2hl(vv.y, h1, l1); f2hl(vv.z, h2, l2); f2hl(vv.w, h3, l3);
    __nv_bfloat162 a, b, c, d;
    a.x = h0; a.y = h1; b.x = h2; b.y = h3;
    c.x = l0; c.y = l1; d.x = l2; d.y = l3;
    ((__nv_bfloat162*)h)[i * 2] = a;
    ((__nv_bfloat162*)h)[i * 2 + 1] = b;
    ((__nv_bfloat162*)l)[i * 2] = c;
    ((__nv_bfloat162*)l)[i * 2 + 1] = d;
}

// W [K,N] f32 -> Wt [N,K] hi/lo bf16, 4 weights fused (blockIdx.z selects)
__global__ void transW_all(const float* __restrict__ W0, const float* __restrict__ W1,
                           const float* __restrict__ W2, const float* __restrict__ W3,
                           __nv_bfloat16* __restrict__ h0p, __nv_bfloat16* __restrict__ l0p,
                           __nv_bfloat16* __restrict__ h1p, __nv_bfloat16* __restrict__ l1p,
                           __nv_bfloat16* __restrict__ h2p, __nv_bfloat16* __restrict__ l2p,
                           __nv_bfloat16* __restrict__ h3p, __nv_bfloat16* __restrict__ l3p) {
    int s = blockIdx.z;
    const float* W = (s == 0) ? W0 : (s == 1) ? W1 : (s == 2) ? W2 : W3;
    __nv_bfloat16* th = (s == 0) ? h0p : (s == 1) ? h1p : (s == 2) ? h2p : h3p;
    __nv_bfloat16* tl = (s == 0) ? l0p : (s == 1) ? l1p : (s == 2) ? l2p : l3p;
    __shared__ float tile[32][33];
    int n = blockIdx.x * 32 + threadIdx.x;
    int k0 = blockIdx.y * 32;
    for (int i = threadIdx.y; i < 32; i += 8)
        tile[i][threadIdx.x] = W[(long long)(k0 + i) * NHID + n];
    __syncthreads();
    int k = k0 + threadIdx.x;
    int nr0 = blockIdx.x * 32;
    for (int i = threadIdx.y; i < 32; i += 8) {
        float f = tile[threadIdx.x][i];
        __nv_bfloat16 h, l;
        f2hl(f, h, l);
        th[(long long)(nr0 + i) * RDIM + k] = h;
        tl[(long long)(nr0 + i) * RDIM + k] = l;
    }
}

// v [b, t, c] bf16 -> vT [b, c, t]  (per-b 1024x1024 transpose, hi and lo)
__global__ void transV(const __nv_bfloat16* __restrict__ vh, const __nv_bfloat16* __restrict__ vl,
                       __nv_bfloat16* __restrict__ oh, __nv_bfloat16* __restrict__ ol) {
    int b = blockIdx.z;
    __shared__ __nv_bfloat16 th[32][33], tl2[32][33];
    long long base = (long long)b * SEQ * NHID;
    int c = blockIdx.x * 32 + threadIdx.x;
    int t0 = blockIdx.y * 32;
    for (int i = threadIdx.y; i < 32; i += 8) {
        th[i][threadIdx.x] = vh[base + (long long)(t0 + i) * NHID + c];
        tl2[i][threadIdx.x] = vl[base + (long long)(t0 + i) * NHID + c];
    }
    __syncthreads();
    int t = t0 + threadIdx.x;
    int c0 = blockIdx.x * 32;
    for (int i = threadIdx.y; i < 32; i += 8) {
        oh[base + (long long)(c0 + i) * SEQ + t] = th[threadIdx.x][i];
        ol[base + (long long)(c0 + i) * SEQ + t] = tl2[threadIdx.x][i];
    }
}

// ======================= shared GEMM building blocks =============================
// full-chunk loader (used for prologue only)
__device__ __forceinline__ void load_mat(uint32_t sBase, const __nv_bfloat16* g, int ld, int kt, int tid) {
#pragma unroll
    for (int i = 0; i < 4; i++) {
        int u = tid + (i << 8);
        int r = u >> 3, cu = u & 7;
        uint32_t off = (uint32_t)(r * 128 + cu * 16);
        off ^= (off >> 3) & 0x70;
        cpa16(sBase + off, g + (long long)r * ld + kt + (cu << 3));
    }
}

__device__ __forceinline__ uint32_t swadr(uint32_t base, int row, int bcol) {
    return base + (uint32_t)(row * 128) + (uint32_t)(bcol ^ ((row & 7) << 4));
}

#define LOADFRAGS(buf, kb) do {                                             \
    _Pragma("unroll")                                                       \
    for (int mi = 0; mi < 2; mi++) {                                        \
        int r_ = wm * 32 + mi * 16 + aRow;                                  \
        ldm_x4(ahf[buf][mi], swadr(aBh, r_, (kb) + aColB));                 \
        ldm_x4(alf[buf][mi], swadr(aBl, r_, (kb) + aColB));                 \
    }                                                                       \
    _Pragma("unroll")                                                       \
    for (int j = 0; j < 4; j++) {                                           \
        int rn_ = wn * 64 + j * 16 + bRow;                                  \
        ldm_x4(bhf[buf][j], swadr(bBh, rn_, (kb) + bColB));                 \
        ldm_x4(blf[buf][j], swadr(bBl, rn_, (kb) + bColB));                 \
    }                                                                       \
} while (0)

#define DOMMAS(buf) do {                                                    \
    _Pragma("unroll")                                                       \
    for (int mi = 0; mi < 2; mi++)                                          \
        _Pragma("unroll")                                                   \
        for (int j = 0; j < 4; j++)                                         \
            _Pragma("unroll")                                               \
            for (int nn = 0; nn < 2; nn++)                                  \
                mma_bf16(acc[mi][2 * j + nn], ahf[buf][mi],                 \
                         bhf[buf][j][nn * 2], bhf[buf][j][nn * 2 + 1]);     \
    _Pragma("unroll")                                                       \
    for (int mi = 0; mi < 2; mi++)                                          \
        _Pragma("unroll")                                                   \
        for (int j = 0; j < 4; j++)                                         \
            _Pragma("unroll")                                               \
            for (int nn = 0; nn < 2; nn++)                                  \
                mma_bf16(acc[mi][2 * j + nn], ahf[buf][mi],                 \
                         blf[buf][j][nn * 2], blf[buf][j][nn * 2 + 1]);     \
    _Pragma("unroll")                                                       \
    for (int mi = 0; mi < 2; mi++)                                          \
        _Pragma("unroll")                                                   \
        for (int j = 0; j < 4; j++)                                         \
            _Pragma("unroll")                                               \
            for (int nn = 0; nn < 2; nn++)                                  \
                mma_bf16(acc[mi][2 * j + nn], alf[buf][mi],                 \
                         bhf[buf][j][nn * 2], bhf[buf][j][nn * 2 + 1]);     \
} while (0)

// ======================= HMMA bf16x3 GEMM ========================================
// C[M,N] = sum_k A[M,K] * Bt[N,K], 3-stage cp.async pipeline.
// Prefetch of chunk c+2 is issued in FOUR slices interleaved with the ks compute
// steps of chunk c, smoothing the LDGSTS burst that was stalling HMMA issue.
// EPI: 0 = hi/lo bf16 out (+opt bias), 1 = f32 out (+bias), 2 = scores (scale+mask f32)
__device__ __forceinline__ void load_chunk(uint32_t stage,
                                           const __nv_bfloat16* Azh, const __nv_bfloat16* Azl, int lda,
                                           const __nv_bfloat16* Bzh, const __nv_bfloat16* Bzl, int ldb,
                                           int kt, int tid) {
    load_mat(stage,         Azh, lda, kt, tid);
    load_mat(stage + 16384, Azl, lda, kt, tid);
    load_mat(stage + 32768, Bzh, ldb, kt, tid);
    load_mat(stage + 49152, Bzl, ldb, kt, tid);
    asm volatile("cp.async.commit_group;" ::: "memory");
}

// one quarter of a chunk's loads (part = 0..3)
__device__ __forceinline__ void load_part(uint32_t stage,
                                          const __nv_bfloat16* Azh, const __nv_bfloat16* Azl, int lda,
                                          const __nv_bfloat16* Bzh, const __nv_bfloat16* Bzl, int ldb,
                                          int kt, int tid, int part) {
    int u = tid + (part << 8);
    int r = u >> 3, cu = u & 7;
    uint32_t off = (uint32_t)(r * 128 + cu * 16);
    off ^= (off >> 3) & 0x70;
    long long ga = (long long)r * lda + kt + (cu << 3);
    long long gb = (long long)r * ldb + kt + (cu << 3);
    cpa16(stage + off,         Azh + ga);
    cpa16(stage + 16384 + off, Azl + ga);
    cpa16(stage + 32768 + off, Bzh + gb);
    cpa16(stage + 49152 + off, Bzl + gb);
}

template <int EPI>
__global__ void __launch_bounds__(256) gemm3(
    const __nv_bfloat16* __restrict__ Ah, const __nv_bfloat16* __restrict__ Al,
    int lda, long long sA1, long long sA2,
    const __nv_bfloat16* __restrict__ Bh, const __nv_bfloat16* __restrict__ Bl,
    int ldb, long long sB1, long long sB2,
    const float* __restrict__ bias,
    float* __restrict__ Cf, __nv_bfloat16* __restrict__ Ch, __nv_bfloat16* __restrict__ Cl,
    int ldc, long long sC1, long long sC2,
    int Ktot, const unsigned char* __restrict__ mask, float scale)
{
    extern __shared__ char smem[];
    uint32_t sb = s2u(smem);
    int tid = threadIdx.x;
    int wid = tid >> 5, lane = tid & 31;
    int wm = wid & 3, wn = wid >> 2;

    int z = blockIdx.z;
    int zb = z / HEADS, zh = z % HEADS;
    int m0 = blockIdx.y * 128, n0 = blockIdx.x * 128;
    const __nv_bfloat16* Azh = Ah + zb * sA1 + zh * sA2 + (long long)m0 * lda;
    const __nv_bfloat16* Azl = Al + zb * sA1 + zh * sA2 + (long long)m0 * lda;
    const __nv_bfloat16* Bzh = Bh + zb * sB1 + zh * sB2 + (long long)n0 * ldb;
    const __nv_bfloat16* Bzl = Bl + zb * sB1 + zh * sB2 + (long long)n0 * ldb;

    float acc[2][8][4];
#pragma unroll
    for (int i = 0; i < 2; i++)
#pragma unroll
        for (int j = 0; j < 8; j++)
#pragma unroll
            for (int q = 0; q < 4; q++) acc[i][j][q] = 0.f;

    int nch = Ktot >> 6;

    load_chunk(sb, Azh, Azl, lda, Bzh, Bzl, ldb, 0, tid);
    if (nch > 1)
        load_chunk(sb + STAGE_BYTES, Azh, Azl, lda, Bzh, Bzl, ldb, 64, tid);

    int aRow = (lane & 15);
    int aColB = (lane >> 4) << 4;
    int bRow = (lane & 7) + ((lane >> 4) << 3);
    int bColB = ((lane >> 3) & 1) << 4;

    uint32_t ahf[2][2][4], alf[2][2][4], bhf[2][4][4], blf[2][4][4];

    for (int c = 0; c < nch; c++) {
        if (c < nch - 1) {
            asm volatile("cp.async.wait_group 1;" ::: "memory");
        } else {
            asm volatile("cp.async.wait_group 0;" ::: "memory");
        }
        __syncthreads();

        bool pf = (c + 2 < nch);
        uint32_t nstage = sb + ((c + 2) % NSTAGE) * STAGE_BYTES;
        int nkt = (c + 2) << 6;

        uint32_t bp = sb + (c % NSTAGE) * STAGE_BYTES;
        uint32_t aBh = bp, aBl = bp + 16384, bBh = bp + 32768, bBl = bp + 49152;

        LOADFRAGS(0, 0);
#pragma unroll
        for (int ks = 0; ks < 4; ks++) {
            if (pf) load_part(nstage, Azh, Azl, lda, Bzh, Bzl, ldb, nkt, tid, ks);
            if (ks < 3) LOADFRAGS((ks + 1) & 1, (ks + 1) << 5);
            DOMMAS(ks & 1);
        }
        if (pf) asm volatile("cp.async.commit_group;" ::: "memory");
    }

    // ---------------- epilogue -----------------
    int gm = m0 + wm * 32;
    int gn = n0 + wn * 64;
    long long cbase = zb * sC1 + zh * sC2;

#pragma unroll
    for (int mi = 0; mi < 2; mi++) {
#pragma unroll
        for (int half = 0; half < 2; half++) {
            int r = gm + mi * 16 + half * 8 + (lane >> 2);
#pragma unroll
            for (int ni = 0; ni < 8; ni++) {
                int cc = gn + ni * 8 + (lane & 3) * 2;
                float f0 = acc[mi][ni][half * 2 + 0];
                float f1 = acc[mi][ni][half * 2 + 1];
                if (EPI == 0) {
                    if (bias) { f0 += bias[cc]; f1 += bias[cc + 1]; }
                    __nv_bfloat16 h0, l0, h1, l1;
                    f2hl(f0, h0, l0); f2hl(f1, h1, l1);
                    __nv_bfloat162 vh2, vl2;
                    vh2.x = h0; vh2.y = h1; vl2.x = l0; vl2.y = l1;
                    *(__nv_bfloat162*)(Ch + cbase + (long long)r * ldc + cc) = vh2;
                    *(__nv_bfloat162*)(Cl + cbase + (long long)r * ldc + cc) = vl2;
                } else if (EPI == 1) {
                    float2 v;
                    v.x = f0 + bias[cc];
                    v.y = f1 + bias[cc + 1];
                    *(float2*)(Cf + cbase + (long long)r * ldc + cc) = v;
                } else {
                    const unsigned char* mb = mask + (long long)zb * SEQ;
                    float2 v;
                    v.x = mb[cc]     ? -1e9f : f0 * scale;
                    v.y = mb[cc + 1] ? -1e9f : f1 * scale;
                    *(float2*)(Cf + cbase + (long long)r * ldc + cc) = v;
                }
            }
        }
    }
}

// ======================= PV GEMM (f32 A, converted in SMEM) ======================
__device__ __forceinline__ void load_pv_chunk(uint32_t stage,
                                              const float* Af, int lda,
                                              const __nv_bfloat16* Bzh, const __nv_bfloat16* Bzl, int ldb,
                                              int kt, int tid) {
#pragma unroll
    for (int i = 0; i < 8; i++) {
        int gid = tid + (i << 8);
        int r = gid >> 4, cu = gid & 15;
        cpa16(stage + (uint32_t)(r * 256 + cu * 16), Af + (long long)r * lda + kt + (cu << 2));
    }
    load_mat(stage + 65536, Bzh, ldb, kt, tid);
    load_mat(stage + 81920, Bzl, ldb, kt, tid);
    asm volatile("cp.async.commit_group;" ::: "memory");
}

__global__ void __launch_bounds__(256) gemm_pv(
    const float* __restrict__ Att,
    const __nv_bfloat16* __restrict__ Vth, const __nv_bfloat16* __restrict__ Vtl,
    __nv_bfloat16* __restrict__ Ch, __nv_bfloat16* __restrict__ Cl)
{
    extern __shared__ char smem[];
    uint32_t sb = s2u(smem);
    int tid = threadIdx.x;
    int wid = tid >> 5, lane = tid & 31;
    int wm = wid & 3, wn = wid >> 2;

    int z = blockIdx.z;
    int zb = z / HEADS, zh = z % HEADS;
    int m0 = blockIdx.y * 128;
    const float* Af = Att + (long long)z * SEQ * SEQ + (long long)m0 * SEQ;
    const __nv_bfloat16* Bzh = Vth + (long long)zb * SEQ * NHID + (long long)zh * DKH * SEQ;
    const __nv_bfloat16* Bzl = Vtl + (long long)zb * SEQ * NHID + (long long)zh * DKH * SEQ;

    float acc[2][8][4];
#pragma unroll
    for (int i = 0; i < 2; i++)
#pragma unroll
        for (int j = 0; j < 8; j++)
#pragma unroll
            for (int q = 0; q < 4; q++) acc[i][j][q] = 0.f;

    const int nch = SEQ >> 6;  // 16

    load_pv_chunk(sb, Af, SEQ, Bzh, Bzl, SEQ, 0, tid);

    int aRow = (lane & 15);
    int aColB = (lane >> 4) << 4;
    int bRow = (lane & 7) + ((lane >> 4) << 3);
    int bColB = ((lane >> 3) & 1) << 4;

    uint32_t ahf[2][2][4], alf[2][2][4], bhf[2][4][4], blf[2][4][4];

    for (int c = 0; c < nch; c++) {
        asm volatile("cp.async.wait_group 0;" ::: "memory");
        __syncthreads();

        uint32_t stage = sb + (uint32_t)(c & 1) * PV_STAGE;

        // prefetch next chunk into the other stage
        if (c + 1 < nch)
            load_pv_chunk(sb + (uint32_t)((c + 1) & 1) * PV_STAGE,
                          Af, SEQ, Bzh, Bzl, SEQ, (c + 1) << 6, tid);

        // convert f32 staging -> hi/lo bf16 swizzled tiles
#pragma unroll
        for (int i = 0; i < 4; i++) {
            int gid = tid + (i << 8);
            int r = gid >> 3, cu = gid & 7;
            uint32_t src = stage + (uint32_t)(r * 256 + cu * 32);
            float4 v0, v1;
            lds128f(v0, src);
            lds128f(v1, src + 16);
            __nv_bfloat16 h0, l0, h1, l1, h2, l2, h3, l3, h4, l4, h5, l5, h6, l6, h7, l7;
            f2hl(v0.x, h0, l0); f2hl(v0.y, h1, l1); f2hl(v0.z, h2, l2); f2hl(v0.w, h3, l3);
            f2hl(v1.x, h4, l4); f2hl(v1.y, h5, l5); f2hl(v1.z, h6, l6); f2hl(v1.w, h7, l7);
            uint32_t off = (uint32_t)(r * 128 + cu * 16);
            off ^= (off >> 3) & 0x70;
            sts128(stage + 32768 + off, pk2(h0, h1), pk2(h2, h3), pk2(h4, h5), pk2(h6, h7));
            sts128(stage + 49152 + off, pk2(l0, l1), pk2(l2, l3), pk2(l4, l5), pk2(l6, l7));
        }
        __syncthreads();

        uint32_t aBh = stage + 32768, aBl = stage + 49152;
        uint32_t bBh = stage + 65536, bBl = stage + 81920;

        LOADFRAGS(0, 0);
#pragma unroll
        for (int ks = 0; ks < 4; ks++) {
            if (ks < 3) LOADFRAGS((ks + 1) & 1, (ks + 1) << 5);
            DOMMAS(ks & 1);
        }
    }

    // epilogue: hi/lo bf16 out, no bias. C row stride NHID, head offset zh*DKH.
    int gm = m0 + wm * 32;
    int gn = wn * 64;
    long long cbase = (long long)zb * SEQ * NHID + (long long)zh * DKH;

#pragma unroll
    for (int mi = 0; mi < 2; mi++) {
#pragma unroll
        for (int half = 0; half < 2; half++) {
            int r = gm + mi * 16 + half * 8 + (lane >> 2);
#pragma unroll
            for (int ni = 0; ni < 8; ni++) {
                int cc = gn + ni * 8 + (lane & 3) * 2;
                float f0 = acc[mi][ni][half * 2 + 0];
                float f1 = acc[mi][ni][half * 2 + 1];
                __nv_bfloat16 h0, l0, h1, l1;
                f2hl(f0, h0, l0); f2hl(f1, h1, l1);
                __nv_bfloat162 vh2, vl2;
                vh2.x = h0; vh2.y = h1; vl2.x = l0; vl2.y = l1;
                *(__nv_bfloat162*)(Ch + cbase + (long long)r * NHID + cc) = vh2;
                *(__nv_bfloat162*)(Cl + cbase + (long long)r * NHID + cc) = vl2;
            }
        }
    }
}

// ======================= softmax (f32 only, in place) ============================
__global__ __launch_bounds__(128) void softmax_rows(float* __restrict__ att)
{
    long long rowi = blockIdx.x;
    float* p = att + rowi * SEQ;
    int t = threadIdx.x;
    int w = t >> 5, l = t & 31;
    __shared__ float smx[4], ssm[4];

    float v[8];
    float mx = -INFINITY;
#pragma unroll
    for (int i = 0; i < 8; i++) {
        v[i] = p[t + i * 128];
        mx = fmaxf(mx, v[i]);
    }
#pragma unroll
    for (int o = 16; o; o >>= 1) mx = fmaxf(mx, __shfl_xor_sync(0xffffffffu, mx, o));
    if (l == 0) smx[w] = mx;
    __syncthreads();
    mx = fmaxf(fmaxf(smx[0], smx[1]), fmaxf(smx[2], smx[3]));

    float s = 0.f;
#pragma unroll
    for (int i = 0; i < 8; i++) {
        v[i] = expf(v[i] - mx);
        s += v[i];
    }
#pragma unroll
    for (int o = 16; o; o >>= 1) s += __shfl_xor_sync(0xffffffffu, s, o);
    if (l == 0) ssm[w] = s;
    __syncthreads();
    s = ssm[0] + ssm[1] + ssm[2] + ssm[3];
    float inv = 1.f / s;
#pragma unroll
    for (int i = 0; i < 8; i++) p[t + i * 128] = v[i] * inv;
}

// ======================= host ====================================================
extern "C" void kernel_launch(void* const* d_in, const int* in_sizes, int n_in,
                              void* d_out, int out_size)
{
    const float* v_in  = (const float*)d_in[0];
    const float* key   = (const float*)d_in[1];
    const float* query = (const float*)d_in[2];
    const void*  mask  = d_in[3];
    const float* Wq = (const float*)d_in[4];
    const float* bq = (const float*)d_in[5];
    const float* Wk = (const float*)d_in[6];
    const float* bk = (const float*)d_in[7];
    const float* Wv = (const float*)d_in[8];
    const float* bv = (const float*)d_in[9];
    const float* Wm = (const float*)d_in[10];
    const float* bm = (const float*)d_in[11];
    float* out = (float*)d_out;

    const long long ATTED_N = (long long)BQ * SEQ * NHID;
    const long long ATT_N   = (long long)BQ * HEADS * SEQ * SEQ;

#define GETP(sym, ty, var) ty* var; cudaGetSymbolAddress((void**)&var, sym)
    GETP(g_inqh, __nv_bfloat16, inqh); GETP(g_inql, __nv_bfloat16, inql);
    GETP(g_inkh, __nv_bfloat16, inkh); GETP(g_inkl, __nv_bfloat16, inkl);
    GETP(g_invh, __nv_bfloat16, invh); GETP(g_invl, __nv_bfloat16, invl);
    GETP(g_wqh, __nv_bfloat16, wqh); GETP(g_wql, __nv_bfloat16, wql);
    GETP(g_wkh, __nv_bfloat16, wkh); GETP(g_wkl, __nv_bfloat16, wkl);
    GETP(g_wvh, __nv_bfloat16, wvh); GETP(g_wvl, __nv_bfloat16, wvl);
    GETP(g_wmh, __nv_bfloat16, wmh); GETP(g_wml, __nv_bfloat16, wml);
    GETP(g_qh, __nv_bfloat16, qh); GETP(g_ql, __nv_bfloat16, ql);
    GETP(g_kh, __nv_bfloat16, kh); GETP(g_kl, __nv_bfloat16, kl);
    GETP(g_vh, __nv_bfloat16, vh); GETP(g_vl, __nv_bfloat16, vl);
    GETP(g_vth, __nv_bfloat16, vth); GETP(g_vtl, __nv_bfloat16, vtl);
    GETP(g_aedh, __nv_bfloat16, aedh); GETP(g_aedl, __nv_bfloat16, aedl);
    GETP(g_attf, float, attf);
    GETP(g_mask, unsigned char, maskp);
#undef GETP

    float* att_ptr;
    float* atted_ptr = out;
    if ((long long)out_size >= ATTED_N + ATT_N) {
        att_ptr = out + ATTED_N;
    } else {
        att_ptr = attf;
    }

    cudaFuncSetAttribute(gemm3<0>, cudaFuncAttributeMaxDynamicSharedMemorySize, GEMM_SMEM);
    cudaFuncSetAttribute(gemm3<1>, cudaFuncAttributeMaxDynamicSharedMemorySize, GEMM_SMEM);
    cudaFuncSetAttribute(gemm3<2>, cudaFuncAttributeMaxDynamicSharedMemorySize, GEMM_SMEM);
    cudaFuncSetAttribute(gemm_pv, cudaFuncAttributeMaxDynamicSharedMemorySize, PV_SMEM);

    const float scale = 1.0f / sqrtf((float)DKH);
    dim3 blk(256);

    // (0) input conversions (fused q/k/v)
    {
        int n4 = (int)(ATTED_N / 4);
        dim3 g((n4 + 255) / 256, 3);
        conv_all<<<g, 256>>>(query, key, v_in, inqh, inql, inkh, inkl, invh, invl, n4);
    }
    // (1) weight transposes (fused)
    {
        dim3 g(32, 32, 4), b(32, 8);
        transW_all<<<g, b>>>(Wq, Wk, Wv, Wm, wqh, wql, wkh, wkl, wvh, wvl, wmh, wml);
    }

    // (2-4) Projections — early so ncu's sample window lands on gemm3
    {
        dim3 grid(NHID / 128, (BQ * SEQ) / 128, 1);
        gemm3<0><<<grid, blk, GEMM_SMEM>>>(inqh, inql, RDIM, 0, 0,
                                           wqh, wql, RDIM, 0, 0, bq,
                                           nullptr, qh, ql, NHID, 0, 0,
                                           RDIM, nullptr, 0.f);
        gemm3<0><<<grid, blk, GEMM_SMEM>>>(inkh, inkl, RDIM, 0, 0,
                                           wkh, wkl, RDIM, 0, 0, bk,
                                           nullptr, kh, kl, NHID, 0, 0,
                                           RDIM, nullptr, 0.f);
        gemm3<0><<<grid, blk, GEMM_SMEM>>>(invh, invl, RDIM, 0, 0,
                                           wvh, wvl, RDIM, 0, 0, bv,
                                           nullptr, vh, vl, NHID, 0, 0,
                                           RDIM, nullptr, 0.f);
    }

    // (5) V transpose per batch
    {
        dim3 g(32, 32, BQ), b(32, 8);
        transV<<<g, b>>>(vh, vl, vth, vtl);
    }

    // (6,7) mask canonicalization
    detect_mask_mode<<<1, 256>>>((const unsigned int*)mask);
    convert_mask<<<(BQ * SEQ + 255) / 256, 256>>>(mask, maskp, BQ * SEQ);

    // (8) Scores: per (b,h): M=N=1024, K=128 -> f32 att with scale+mask
    {
        dim3 grid(SEQ / 128, SEQ / 128, BQ * HEADS);
        gemm3<2><<<grid, blk, GEMM_SMEM>>>(qh, ql, NHID, (long long)SEQ * NHID, DKH,
                                           kh, kl, NHID, (long long)SEQ * NHID, DKH,
                                           nullptr,
                                           att_ptr, nullptr, nullptr, SEQ,
                                           (long long)HEADS * SEQ * SEQ, (long long)SEQ * SEQ,
                                           DKH, maskp, scale);
    }

    // (9) Softmax in place (f32 only)
    softmax_rows<<<(unsigned)(BQ * HEADS * SEQ), dim3(128)>>>(att_ptr);

    // (10) PV: f32 att converted in SMEM -> hi/lo atted
    {
        dim3 grid(1, SEQ / 128, BQ * HEADS);
        gemm_pv<<<grid, blk, PV_SMEM>>>(att_ptr, vth, vtl, aedh, aedl);
    }

    // (11) Output projection
    {
        dim3 grid(NHID / 128, (BQ * SEQ) / 128, 1);
        gemm3<1><<<grid, blk, GEMM_SMEM>>>(aedh, aedl, NHID, 0, 0,
                                           wmh, wml, NHID, 0, 0, bm,
                                           atted_ptr, nullptr, nullptr, NHID, 0, 0,
                                           NHID, nullptr, 0.f);
    }
}

// round 11
// speedup vs baseline: 1.0866x; 1.0563x over previous
#include <cuda_runtime.h>
#include <cuda_bf16.h>
#include <math.h>
#include <stdint.h>
#include <string.h>

#define BQ 16
#define SEQ 1024
#define RDIM 1024
#define NHID 1024
#define HEADS 8
#define DKH 128

// ======================= static scratch ==========================================
__device__ __nv_bfloat16 g_inqh[(size_t)BQ * SEQ * RDIM], g_inql[(size_t)BQ * SEQ * RDIM];
__device__ __nv_bfloat16 g_inkh[(size_t)BQ * SEQ * RDIM], g_inkl[(size_t)BQ * SEQ * RDIM];
__device__ __nv_bfloat16 g_invh[(size_t)BQ * SEQ * RDIM], g_invl[(size_t)BQ * SEQ * RDIM];
__device__ __nv_bfloat16 g_wqh[(size_t)NHID * RDIM], g_wql[(size_t)NHID * RDIM];
__device__ __nv_bfloat16 g_wkh[(size_t)NHID * RDIM], g_wkl[(size_t)NHID * RDIM];
__device__ __nv_bfloat16 g_wvh[(size_t)NHID * RDIM], g_wvl[(size_t)NHID * RDIM];
__device__ __nv_bfloat16 g_wmh[(size_t)NHID * NHID], g_wml[(size_t)NHID * NHID];
__device__ __nv_bfloat16 g_qh[(size_t)BQ * SEQ * NHID], g_ql[(size_t)BQ * SEQ * NHID];
__device__ __nv_bfloat16 g_kh[(size_t)BQ * SEQ * NHID], g_kl[(size_t)BQ * SEQ * NHID];
__device__ __nv_bfloat16 g_vh[(size_t)BQ * SEQ * NHID], g_vl[(size_t)BQ * SEQ * NHID];
__device__ __nv_bfloat16 g_vth[(size_t)BQ * SEQ * NHID], g_vtl[(size_t)BQ * SEQ * NHID];
__device__ __nv_bfloat16 g_aedh[(size_t)BQ * SEQ * NHID], g_aedl[(size_t)BQ * SEQ * NHID];
__device__ float g_attf[(size_t)BQ * HEADS * SEQ * SEQ]; // fallback if att not in d_out
__device__ unsigned char g_mask[(size_t)BQ * SEQ];
__device__ int g_mask_mode;

// ======================= small helpers ===========================================
__device__ __forceinline__ uint32_t s2u(const void* p) {
    uint32_t a;
    asm("{ .reg .u64 t; cvta.to.shared.u64 t, %1; cvt.u32.u64 %0, t; }" : "=r"(a) : "l"(p));
    return a;
}
__device__ __forceinline__ void f2hl(float x, __nv_bfloat16& h, __nv_bfloat16& l) {
    h = __float2bfloat16(x);
    l = __float2bfloat16(x - __bfloat162float(h));
}
__device__ __forceinline__ uint32_t pk2(__nv_bfloat16 a, __nv_bfloat16 b) {
    __nv_bfloat162 t; t.x = a; t.y = b;
    uint32_t u; memcpy(&u, &t, 4);
    return u;
}
__device__ __forceinline__ void cpa16(uint32_t s, const void* g) {
    asm volatile("cp.async.cg.shared.global [%0], [%1], 16;" :: "r"(s), "l"(g) : "memory");
}
__device__ __forceinline__ void ldm_x4(uint32_t r[4], uint32_t addr) {
    asm volatile("ldmatrix.sync.aligned.m8n8.x4.shared.b16 {%0,%1,%2,%3}, [%4];"
                 : "=r"(r[0]), "=r"(r[1]), "=r"(r[2]), "=r"(r[3]) : "r"(addr));
}
__device__ __forceinline__ void mma_bf16(float* c, const uint32_t* a, uint32_t b0, uint32_t b1) {
    asm volatile(
        "mma.sync.aligned.m16n8k16.row.col.f32.bf16.bf16.f32 "
        "{%0,%1,%2,%3}, {%4,%5,%6,%7}, {%8,%9}, {%0,%1,%2,%3};"
        : "+f"(c[0]), "+f"(c[1]), "+f"(c[2]), "+f"(c[3])
        : "r"(a[0]), "r"(a[1]), "r"(a[2]), "r"(a[3]), "r"(b0), "r"(b1));
}
__device__ __forceinline__ void lds128f(float4& v, uint32_t a) {
    asm volatile("ld.shared.v4.f32 {%0,%1,%2,%3}, [%4];"
                 : "=f"(v.x), "=f"(v.y), "=f"(v.z), "=f"(v.w) : "r"(a));
}
__device__ __forceinline__ void sts128(uint32_t a, uint32_t x0, uint32_t x1, uint32_t x2, uint32_t x3) {
    asm volatile("st.shared.v4.b32 [%0], {%1,%2,%3,%4};"
                 :: "r"(a), "r"(x0), "r"(x1), "r"(x2), "r"(x3) : "memory");
}

// gemm3: 128x64 tile, 2 stages of 48KB (Ah 16K, Al 16K, Bh 8K, Bl 8K)
#define G3_STAGE 49152
#define GEMM_SMEM (2 * G3_STAGE)           // 98304 -> 2 CTAs/SM
// PV: unchanged
#define PV_STAGE 98304
#define PV_SMEM (2 * PV_STAGE)             // 196608

// ======================= mask canonicalization ===================================
__global__ void detect_mask_mode(const unsigned int* __restrict__ m) {
    __shared__ int s_non01f, s_f32w;
    if (threadIdx.x == 0) { s_non01f = 0; s_f32w = 0; }
    __syncthreads();
    int ln = 0, lf = 0;
    for (int i = threadIdx.x; i < 4096; i += blockDim.x) {
        unsigned int w = m[i];
        if (w == 0x3F800000u) lf = 1;
        else if (w > 1u) ln = 1;
    }
    if (ln) atomicOr(&s_non01f, 1);
    if (lf) atomicOr(&s_f32w, 1);
    __syncthreads();
    if (threadIdx.x == 0) {
        if (s_non01f) g_mask_mode = 0;
        else if (s_f32w) g_mask_mode = 2;
        else g_mask_mode = 1;
    }
}
__global__ void convert_mask(const void* __restrict__ m, unsigned char* __restrict__ outm, int n) {
    int i = blockIdx.x * blockDim.x + threadIdx.x;
    if (i >= n) return;
    int mode = g_mask_mode;
    unsigned char r;
    if (mode == 0)      r = ((const unsigned char*)m)[i] ? 1 : 0;
    else if (mode == 1) r = ((const int*)m)[i] ? 1 : 0;
    else                r = (((const float*)m)[i] != 0.0f) ? 1 : 0;
    outm[i] = r;
}

// ======================= conversions (fused) =====================================
__global__ void conv_all(const float* __restrict__ q, const float* __restrict__ k,
                         const float* __restrict__ v,
                         __nv_bfloat16* __restrict__ qh, __nv_bfloat16* __restrict__ ql,
                         __nv_bfloat16* __restrict__ kh, __nv_bfloat16* __restrict__ kl,
                         __nv_bfloat16* __restrict__ vh, __nv_bfloat16* __restrict__ vl,
                         int n4) {
    int i = blockIdx.x * blockDim.x + threadIdx.x;
    if (i >= n4) return;
    int sel = blockIdx.y;
    const float* s = (sel == 0) ? q : (sel == 1) ? k : v;
    __nv_bfloat16* h = (sel == 0) ? qh : (sel == 1) ? kh : vh;
    __nv_bfloat16* l = (sel == 0) ? ql : (sel == 1) ? kl : vl;
    float4 vv = ((const float4*)s)[i];
    __nv_bfloat16 h0, l0, h1, l1, h2, l2, h3, l3;
    f2hl(vv.x, h0, l0); f2hl(vv.y, h1, l1); f2hl(vv.z, h2, l2); f2hl(vv.w, h3, l3);
    __nv_bfloat162 a, b, c, d;
    a.x = h0; a.y = h1; b.x = h2; b.y = h3;
    c.x = l0; c.y = l1; d.x = l2; d.y = l3;
    ((__nv_bfloat162*)h)[i * 2] = a;
    ((__nv_bfloat162*)h)[i * 2 + 1] = b;
    ((__nv_bfloat162*)l)[i * 2] = c;
    ((__nv_bfloat162*)l)[i * 2 + 1] = d;
}

// W [K,N] f32 -> Wt [N,K] hi/lo bf16, 4 weights fused (blockIdx.z selects)
__global__ void transW_all(const float* __restrict__ W0, const float* __restrict__ W1,
                           const float* __restrict__ W2, const float* __restrict__ W3,
                           __nv_bfloat16* __restrict__ h0p, __nv_bfloat16* __restrict__ l0p,
                           __nv_bfloat16* __restrict__ h1p, __nv_bfloat16* __restrict__ l1p,
                           __nv_bfloat16* __restrict__ h2p, __nv_bfloat16* __restrict__ l2p,
                           __nv_bfloat16* __restrict__ h3p, __nv_bfloat16* __restrict__ l3p) {
    int s = blockIdx.z;
    const float* W = (s == 0) ? W0 : (s == 1) ? W1 : (s == 2) ? W2 : W3;
    __nv_bfloat16* th = (s == 0) ? h0p : (s == 1) ? h1p : (s == 2) ? h2p : h3p;
    __nv_bfloat16* tl = (s == 0) ? l0p : (s == 1) ? l1p : (s == 2) ? l2p : l3p;
    __shared__ float tile[32][33];
    int n = blockIdx.x * 32 + threadIdx.x;
    int k0 = blockIdx.y * 32;
    for (int i = threadIdx.y; i < 32; i += 8)
        tile[i][threadIdx.x] = W[(long long)(k0 + i) * NHID + n];
    __syncthreads();
    int k = k0 + threadIdx.x;
    int nr0 = blockIdx.x * 32;
    for (int i = threadIdx.y; i < 32; i += 8) {
        float f = tile[threadIdx.x][i];
        __nv_bfloat16 h, l;
        f2hl(f, h, l);
        th[(long long)(nr0 + i) * RDIM + k] = h;
        tl[(long long)(nr0 + i) * RDIM + k] = l;
    }
}

// v [b, t, c] bf16 -> vT [b, c, t]  (per-b 1024x1024 transpose, hi and lo)
__global__ void transV(const __nv_bfloat16* __restrict__ vh, const __nv_bfloat16* __restrict__ vl,
                       __nv_bfloat16* __restrict__ oh, __nv_bfloat16* __restrict__ ol) {
    int b = blockIdx.z;
    __shared__ __nv_bfloat16 th[32][33], tl2[32][33];
    long long base = (long long)b * SEQ * NHID;
    int c = blockIdx.x * 32 + threadIdx.x;
    int t0 = blockIdx.y * 32;
    for (int i = threadIdx.y; i < 32; i += 8) {
        th[i][threadIdx.x] = vh[base + (long long)(t0 + i) * NHID + c];
        tl2[i][threadIdx.x] = vl[base + (long long)(t0 + i) * NHID + c];
    }
    __syncthreads();
    int t = t0 + threadIdx.x;
    int c0 = blockIdx.x * 32;
    for (int i = threadIdx.y; i < 32; i += 8) {
        oh[base + (long long)(c0 + i) * SEQ + t] = th[threadIdx.x][i];
        ol[base + (long long)(c0 + i) * SEQ + t] = tl2[threadIdx.x][i];
    }
}

// ======================= shared GEMM building blocks =============================
// 128-row tile loader (16KB): used by PV B tiles and gemm3 A tiles
__device__ __forceinline__ void load_mat(uint32_t sBase, const __nv_bfloat16* g, int ld, int kt, int tid) {
#pragma unroll
    for (int i = 0; i < 4; i++) {
        int u = tid + (i << 8);
        int r = u >> 3, cu = u & 7;
        uint32_t off = (uint32_t)(r * 128 + cu * 16);
        off ^= (off >> 3) & 0x70;
        cpa16(sBase + off, g + (long long)r * ld + kt + (cu << 3));
    }
}
// 64-row tile loader (8KB): gemm3 B tiles
__device__ __forceinline__ void load_mat64(uint32_t sBase, const __nv_bfloat16* g, int ld, int kt, int tid) {
#pragma unroll
    for (int i = 0; i < 2; i++) {
        int u = tid + (i << 8);
        int r = u >> 3, cu = u & 7;
        uint32_t off = (uint32_t)(r * 128 + cu * 16);
        off ^= (off >> 3) & 0x70;
        cpa16(sBase + off, g + (long long)r * ld + kt + (cu << 3));
    }
}

__device__ __forceinline__ uint32_t swadr(uint32_t base, int row, int bcol) {
    return base + (uint32_t)(row * 128) + (uint32_t)(bcol ^ ((row & 7) << 4));
}

// PV macros (128-wide N warp tile, 64 cols per warp group)
#define LOADFRAGS(buf, kb) do {                                             \
    _Pragma("unroll")                                                       \
    for (int mi = 0; mi < 2; mi++) {                                        \
        int r_ = wm * 32 + mi * 16 + aRow;                                  \
        ldm_x4(ahf[buf][mi], swadr(aBh, r_, (kb) + aColB));                 \
        ldm_x4(alf[buf][mi], swadr(aBl, r_, (kb) + aColB));                 \
    }                                                                       \
    _Pragma("unroll")                                                       \
    for (int j = 0; j < 4; j++) {                                           \
        int rn_ = wn * 64 + j * 16 + bRow;                                  \
        ldm_x4(bhf[buf][j], swadr(bBh, rn_, (kb) + bColB));                 \
        ldm_x4(blf[buf][j], swadr(bBl, rn_, (kb) + bColB));                 \
    }                                                                       \
} while (0)

#define DOMMAS(buf) do {                                                    \
    _Pragma("unroll")                                                       \
    for (int mi = 0; mi < 2; mi++)                                          \
        _Pragma("unroll")                                                   \
        for (int j = 0; j < 4; j++)                                         \
            _Pragma("unroll")                                               \
            for (int nn = 0; nn < 2; nn++)                                  \
                mma_bf16(acc[mi][2 * j + nn], ahf[buf][mi],                 \
                         bhf[buf][j][nn * 2], bhf[buf][j][nn * 2 + 1]);     \
    _Pragma("unroll")                                                       \
    for (int mi = 0; mi < 2; mi++)                                          \
        _Pragma("unroll")                                                   \
        for (int j = 0; j < 4; j++)                                         \
            _Pragma("unroll")                                               \
            for (int nn = 0; nn < 2; nn++)                                  \
                mma_bf16(acc[mi][2 * j + nn], ahf[buf][mi],                 \
                         blf[buf][j][nn * 2], blf[buf][j][nn * 2 + 1]);     \
    _Pragma("unroll")                                                       \
    for (int mi = 0; mi < 2; mi++)                                          \
        _Pragma("unroll")                                                   \
        for (int j = 0; j < 4; j++)                                         \
            _Pragma("unroll")                                               \
            for (int nn = 0; nn < 2; nn++)                                  \
                mma_bf16(acc[mi][2 * j + nn], alf[buf][mi],                 \
                         bhf[buf][j][nn * 2], bhf[buf][j][nn * 2 + 1]);     \
} while (0)

// ======================= HMMA bf16x3 GEMM (128x64 tile, 2 CTAs/SM) ===============
// C[M,N] = sum_k A[M,K] * Bt[N,K]. 8 warps, warp tile 32x32 (wm=wid&3, wn=wid>>2).
// 2-stage: stage layout Ah@0(16K), Al@16K, Bh@32K(8K), Bl@40K.
// EPI: 0 = hi/lo bf16 out (+opt bias), 1 = f32 out (+bias), 2 = scores (scale+mask f32)
__device__ __forceinline__ void g3_load_chunk(uint32_t stage,
                                              const __nv_bfloat16* Azh, const __nv_bfloat16* Azl, int lda,
                                              const __nv_bfloat16* Bzh, const __nv_bfloat16* Bzl, int ldb,
                                              int kt, int tid) {
    load_mat(stage,           Azh, lda, kt, tid);
    load_mat(stage + 16384,   Azl, lda, kt, tid);
    load_mat64(stage + 32768, Bzh, ldb, kt, tid);
    load_mat64(stage + 40960, Bzl, ldb, kt, tid);
    asm volatile("cp.async.commit_group;" ::: "memory");
}

template <int EPI>
__global__ void __launch_bounds__(256, 2) gemm3(
    const __nv_bfloat16* __restrict__ Ah, const __nv_bfloat16* __restrict__ Al,
    int lda, long long sA1, long long sA2,
    const __nv_bfloat16* __restrict__ Bh, const __nv_bfloat16* __restrict__ Bl,
    int ldb, long long sB1, long long sB2,
    const float* __restrict__ bias,
    float* __restrict__ Cf, __nv_bfloat16* __restrict__ Ch, __nv_bfloat16* __restrict__ Cl,
    int ldc, long long sC1, long long sC2,
    int Ktot, const unsigned char* __restrict__ mask, float scale)
{
    extern __shared__ char smem[];
    uint32_t sb = s2u(smem);
    int tid = threadIdx.x;
    int wid = tid >> 5, lane = tid & 31;
    int wm = wid & 3, wn = wid >> 2;   // warp tile: rows wm*32.., cols wn*32..

    int z = blockIdx.z;
    int zb = z / HEADS, zh = z % HEADS;
    int m0 = blockIdx.y * 128, n0 = blockIdx.x * 64;
    const __nv_bfloat16* Azh = Ah + zb * sA1 + zh * sA2 + (long long)m0 * lda;
    const __nv_bfloat16* Azl = Al + zb * sA1 + zh * sA2 + (long long)m0 * lda;
    const __nv_bfloat16* Bzh = Bh + zb * sB1 + zh * sB2 + (long long)n0 * ldb;
    const __nv_bfloat16* Bzl = Bl + zb * sB1 + zh * sB2 + (long long)n0 * ldb;

    float acc[2][4][4];
#pragma unroll
    for (int i = 0; i < 2; i++)
#pragma unroll
        for (int j = 0; j < 4; j++)
#pragma unroll
            for (int q = 0; q < 4; q++) acc[i][j][q] = 0.f;

    int nch = Ktot >> 6;

    g3_load_chunk(sb, Azh, Azl, lda, Bzh, Bzl, ldb, 0, tid);
    if (nch > 1)
        g3_load_chunk(sb + G3_STAGE, Azh, Azl, lda, Bzh, Bzl, ldb, 64, tid);

    int aRow = (lane & 15);
    int aColB = (lane >> 4) << 4;
    int bRow = (lane & 7) + ((lane >> 4) << 3);
    int bColB = ((lane >> 3) & 1) << 4;

    for (int c = 0; c < nch; c++) {
        if (c < nch - 1) {
            asm volatile("cp.async.wait_group 1;" ::: "memory");
        } else {
            asm volatile("cp.async.wait_group 0;" ::: "memory");
        }
        __syncthreads();

        uint32_t bp = sb + (uint32_t)(c & 1) * G3_STAGE;
        uint32_t aBh = bp, aBl = bp + 16384, bBh = bp + 32768, bBl = bp + 40960;

#pragma unroll
        for (int ks = 0; ks < 4; ks++) {
            int kb = ks << 5;
            uint32_t ah[2][4], al[2][4], bh[2][4], bl[2][4];
#pragma unroll
            for (int mi = 0; mi < 2; mi++) {
                int r = wm * 32 + mi * 16 + aRow;
                ldm_x4(ah[mi], swadr(aBh, r, kb + aColB));
                ldm_x4(al[mi], swadr(aBl, r, kb + aColB));
            }
#pragma unroll
            for (int j = 0; j < 2; j++) {
                int rn = wn * 32 + j * 16 + bRow;
                ldm_x4(bh[j], swadr(bBh, rn, kb + bColB));
                ldm_x4(bl[j], swadr(bBl, rn, kb + bColB));
            }
            // hh
#pragma unroll
            for (int mi = 0; mi < 2; mi++)
#pragma unroll
                for (int j = 0; j < 2; j++)
#pragma unroll
                    for (int nn = 0; nn < 2; nn++)
                        mma_bf16(acc[mi][2 * j + nn], ah[mi], bh[j][nn * 2], bh[j][nn * 2 + 1]);
            // hl
#pragma unroll
            for (int mi = 0; mi < 2; mi++)
#pragma unroll
                for (int j = 0; j < 2; j++)
#pragma unroll
                    for (int nn = 0; nn < 2; nn++)
                        mma_bf16(acc[mi][2 * j + nn], ah[mi], bl[j][nn * 2], bl[j][nn * 2 + 1]);
            // lh
#pragma unroll
            for (int mi = 0; mi < 2; mi++)
#pragma unroll
                for (int j = 0; j < 2; j++)
#pragma unroll
                    for (int nn = 0; nn < 2; nn++)
                        mma_bf16(acc[mi][2 * j + nn], al[mi], bh[j][nn * 2], bh[j][nn * 2 + 1]);
        }
        __syncthreads();

        // prefetch chunk c+2 into the stage just freed
        if (c + 2 < nch)
            g3_load_chunk(sb + (uint32_t)(c & 1) * G3_STAGE,
                          Azh, Azl, lda, Bzh, Bzl, ldb, (c + 2) << 6, tid);
    }

    // ---------------- epilogue -----------------
    int gm = m0 + wm * 32;
    int gn = n0 + wn * 32;
    long long cbase = zb * sC1 + zh * sC2;

#pragma unroll
    for (int mi = 0; mi < 2; mi++) {
#pragma unroll
        for (int half = 0; half < 2; half++) {
            int r = gm + mi * 16 + half * 8 + (lane >> 2);
#pragma unroll
            for (int ni = 0; ni < 4; ni++) {
                int cc = gn + ni * 8 + (lane & 3) * 2;
                float f0 = acc[mi][ni][half * 2 + 0];
                float f1 = acc[mi][ni][half * 2 + 1];
                if (EPI == 0) {
                    if (bias) { f0 += bias[cc]; f1 += bias[cc + 1]; }
                    __nv_bfloat16 h0, l0, h1, l1;
                    f2hl(f0, h0, l0); f2hl(f1, h1, l1);
                    __nv_bfloat162 vh2, vl2;
                    vh2.x = h0; vh2.y = h1; vl2.x = l0; vl2.y = l1;
                    *(__nv_bfloat162*)(Ch + cbase + (long long)r * ldc + cc) = vh2;
                    *(__nv_bfloat162*)(Cl + cbase + (long long)r * ldc + cc) = vl2;
                } else if (EPI == 1) {
                    float2 v;
                    v.x = f0 + bias[cc];
                    v.y = f1 + bias[cc + 1];
                    *(float2*)(Cf + cbase + (long long)r * ldc + cc) = v;
                } else {
                    const unsigned char* mb = mask + (long long)zb * SEQ;
                    float2 v;
                    v.x = mb[cc]     ? -1e9f : f0 * scale;
                    v.y = mb[cc + 1] ? -1e9f : f1 * scale;
                    *(float2*)(Cf + cbase + (long long)r * ldc + cc) = v;
                }
            }
        }
    }
}

// ======================= PV GEMM (f32 A, converted in SMEM) ======================
__device__ __forceinline__ void load_pv_chunk(uint32_t stage,
                                              const float* Af, int lda,
                                              const __nv_bfloat16* Bzh, const __nv_bfloat16* Bzl, int ldb,
                                              int kt, int tid) {
#pragma unroll
    for (int i = 0; i < 8; i++) {
        int gid = tid + (i << 8);
        int r = gid >> 4, cu = gid & 15;
        cpa16(stage + (uint32_t)(r * 256 + cu * 16), Af + (long long)r * lda + kt + (cu << 2));
    }
    load_mat(stage + 65536, Bzh, ldb, kt, tid);
    load_mat(stage + 81920, Bzl, ldb, kt, tid);
    asm volatile("cp.async.commit_group;" ::: "memory");
}

__global__ void __launch_bounds__(256) gemm_pv(
    const float* __restrict__ Att,
    const __nv_bfloat16* __restrict__ Vth, const __nv_bfloat16* __restrict__ Vtl,
    __nv_bfloat16* __restrict__ Ch, __nv_bfloat16* __restrict__ Cl)
{
    extern __shared__ char smem[];
    uint32_t sb = s2u(smem);
    int tid = threadIdx.x;
    int wid = tid >> 5, lane = tid & 31;
    int wm = wid & 3, wn = wid >> 2;

    int z = blockIdx.z;
    int zb = z / HEADS, zh = z % HEADS;
    int m0 = blockIdx.y * 128;
    const float* Af = Att + (long long)z * SEQ * SEQ + (long long)m0 * SEQ;
    const __nv_bfloat16* Bzh = Vth + (long long)zb * SEQ * NHID + (long long)zh * DKH * SEQ;
    const __nv_bfloat16* Bzl = Vtl + (long long)zb * SEQ * NHID + (long long)zh * DKH * SEQ;

    float acc[2][8][4];
#pragma unroll
    for (int i = 0; i < 2; i++)
#pragma unroll
        for (int j = 0; j < 8; j++)
#pragma unroll
            for (int q = 0; q < 4; q++) acc[i][j][q] = 0.f;

    const int nch = SEQ >> 6;  // 16

    load_pv_chunk(sb, Af, SEQ, Bzh, Bzl, SEQ, 0, tid);

    int aRow = (lane & 15);
    int aColB = (lane >> 4) << 4;
    int bRow = (lane & 7) + ((lane >> 4) << 3);
    int bColB = ((lane >> 3) & 1) << 4;

    uint32_t ahf[2][2][4], alf[2][2][4], bhf[2][4][4], blf[2][4][4];

    for (int c = 0; c < nch; c++) {
        asm volatile("cp.async.wait_group 0;" ::: "memory");
        __syncthreads();

        uint32_t stage = sb + (uint32_t)(c & 1) * PV_STAGE;

        // prefetch next chunk into the other stage
        if (c + 1 < nch)
            load_pv_chunk(sb + (uint32_t)((c + 1) & 1) * PV_STAGE,
                          Af, SEQ, Bzh, Bzl, SEQ, (c + 1) << 6, tid);

        // convert f32 staging -> hi/lo bf16 swizzled tiles
#pragma unroll
        for (int i = 0; i < 4; i++) {
            int gid = tid + (i << 8);
            int r = gid >> 3, cu = gid & 7;
            uint32_t src = stage + (uint32_t)(r * 256 + cu * 32);
            float4 v0, v1;
            lds128f(v0, src);
            lds128f(v1, src + 16);
            __nv_bfloat16 h0, l0, h1, l1, h2, l2, h3, l3, h4, l4, h5, l5, h6, l6, h7, l7;
            f2hl(v0.x, h0, l0); f2hl(v0.y, h1, l1); f2hl(v0.z, h2, l2); f2hl(v0.w, h3, l3);
            f2hl(v1.x, h4, l4); f2hl(v1.y, h5, l5); f2hl(v1.z, h6, l6); f2hl(v1.w, h7, l7);
            uint32_t off = (uint32_t)(r * 128 + cu * 16);
            off ^= (off >> 3) & 0x70;
            sts128(stage + 32768 + off, pk2(h0, h1), pk2(h2, h3), pk2(h4, h5), pk2(h6, h7));
            sts128(stage + 49152 + off, pk2(l0, l1), pk2(l2, l3), pk2(l4, l5), pk2(l6, l7));
        }
        __syncthreads();

        uint32_t aBh = stage + 32768, aBl = stage + 49152;
        uint32_t bBh = stage + 65536, bBl = stage + 81920;

        LOADFRAGS(0, 0);
#pragma unroll
        for (int ks = 0; ks < 4; ks++) {
            if (ks < 3) LOADFRAGS((ks + 1) & 1, (ks + 1) << 5);
            DOMMAS(ks & 1);
        }
    }

    // epilogue: hi/lo bf16 out, no bias. C row stride NHID, head offset zh*DKH.
    int gm = m0 + wm * 32;
    int gn = wn * 64;
    long long cbase = (long long)zb * SEQ * NHID + (long long)zh * DKH;

#pragma unroll
    for (int mi = 0; mi < 2; mi++) {
#pragma unroll
        for (int half = 0; half < 2; half++) {
            int r = gm + mi * 16 + half * 8 + (lane >> 2);
#pragma unroll
            for (int ni = 0; ni < 8; ni++) {
                int cc = gn + ni * 8 + (lane & 3) * 2;
                float f0 = acc[mi][ni][half * 2 + 0];
                float f1 = acc[mi][ni][half * 2 + 1];
                __nv_bfloat16 h0, l0, h1, l1;
                f2hl(f0, h0, l0); f2hl(f1, h1, l1);
                __nv_bfloat162 vh2, vl2;
                vh2.x = h0; vh2.y = h1; vl2.x = l0; vl2.y = l1;
                *(__nv_bfloat162*)(Ch + cbase + (long long)r * NHID + cc) = vh2;
                *(__nv_bfloat162*)(Cl + cbase + (long long)r * NHID + cc) = vl2;
            }
        }
    }
}

// ======================= softmax (f32 only, in place) ============================
__global__ __launch_bounds__(128) void softmax_rows(float* __restrict__ att)
{
    long long rowi = blockIdx.x;
    float* p = att + rowi * SEQ;
    int t = threadIdx.x;
    int w = t >> 5, l = t & 31;
    __shared__ float smx[4], ssm[4];

    float v[8];
    float mx = -INFINITY;
#pragma unroll
    for (int i = 0; i < 8; i++) {
        v[i] = p[t + i * 128];
        mx = fmaxf(mx, v[i]);
    }
#pragma unroll
    for (int o = 16; o; o >>= 1) mx = fmaxf(mx, __shfl_xor_sync(0xffffffffu, mx, o));
    if (l == 0) smx[w] = mx;
    __syncthreads();
    mx = fmaxf(fmaxf(smx[0], smx[1]), fmaxf(smx[2], smx[3]));

    float s = 0.f;
#pragma unroll
    for (int i = 0; i < 8; i++) {
        v[i] = expf(v[i] - mx);
        s += v[i];
    }
#pragma unroll
    for (int o = 16; o; o >>= 1) s += __shfl_xor_sync(0xffffffffu, s, o);
    if (l == 0) ssm[w] = s;
    __syncthreads();
    s = ssm[0] + ssm[1] + ssm[2] + ssm[3];
    float inv = 1.f / s;
#pragma unroll
    for (int i = 0; i < 8; i++) p[t + i * 128] = v[i] * inv;
}

// ======================= host ====================================================
extern "C" void kernel_launch(void* const* d_in, const int* in_sizes, int n_in,
                              void* d_out, int out_size)
{
    const float* v_in  = (const float*)d_in[0];
    const float* key   = (const float*)d_in[1];
    const float* query = (const float*)d_in[2];
    const void*  mask  = d_in[3];
    const float* Wq = (const float*)d_in[4];
    const float* bq = (const float*)d_in[5];
    const float* Wk = (const float*)d_in[6];
    const float* bk = (const float*)d_in[7];
    const float* Wv = (const float*)d_in[8];
    const float* bv = (const float*)d_in[9];
    const float* Wm = (const float*)d_in[10];
    const float* bm = (const float*)d_in[11];
    float* out = (float*)d_out;

    const long long ATTED_N = (long long)BQ * SEQ * NHID;
    const long long ATT_N   = (long long)BQ * HEADS * SEQ * SEQ;

#define GETP(sym, ty, var) ty* var; cudaGetSymbolAddress((void**)&var, sym)
    GETP(g_inqh, __nv_bfloat16, inqh); GETP(g_inql, __nv_bfloat16, inql);
    GETP(g_inkh, __nv_bfloat16, inkh); GETP(g_inkl, __nv_bfloat16, inkl);
    GETP(g_invh, __nv_bfloat16, invh); GETP(g_invl, __nv_bfloat16, invl);
    GETP(g_wqh, __nv_bfloat16, wqh); GETP(g_wql, __nv_bfloat16, wql);
    GETP(g_wkh, __nv_bfloat16, wkh); GETP(g_wkl, __nv_bfloat16, wkl);
    GETP(g_wvh, __nv_bfloat16, wvh); GETP(g_wvl, __nv_bfloat16, wvl);
    GETP(g_wmh, __nv_bfloat16, wmh); GETP(g_wml, __nv_bfloat16, wml);
    GETP(g_qh, __nv_bfloat16, qh); GETP(g_ql, __nv_bfloat16, ql);
    GETP(g_kh, __nv_bfloat16, kh); GETP(g_kl, __nv_bfloat16, kl);
    GETP(g_vh, __nv_bfloat16, vh); GETP(g_vl, __nv_bfloat16, vl);
    GETP(g_vth, __nv_bfloat16, vth); GETP(g_vtl, __nv_bfloat16, vtl);
    GETP(g_aedh, __nv_bfloat16, aedh); GETP(g_aedl, __nv_bfloat16, aedl);
    GETP(g_attf, float, attf);
    GETP(g_mask, unsigned char, maskp);
#undef GETP

    float* att_ptr;
    float* atted_ptr = out;
    if ((long long)out_size >= ATTED_N + ATT_N) {
        att_ptr = out + ATTED_N;
    } else {
        att_ptr = attf;
    }

    cudaFuncSetAttribute(gemm3<0>, cudaFuncAttributeMaxDynamicSharedMemorySize, GEMM_SMEM);
    cudaFuncSetAttribute(gemm3<1>, cudaFuncAttributeMaxDynamicSharedMemorySize, GEMM_SMEM);
    cudaFuncSetAttribute(gemm3<2>, cudaFuncAttributeMaxDynamicSharedMemorySize, GEMM_SMEM);
    cudaFuncSetAttribute(gemm_pv, cudaFuncAttributeMaxDynamicSharedMemorySize, PV_SMEM);

    const float scale = 1.0f / sqrtf((float)DKH);
    dim3 blk(256);

    // (0) input conversions (fused q/k/v)
    {
        int n4 = (int)(ATTED_N / 4);
        dim3 g((n4 + 255) / 256, 3);
        conv_all<<<g, 256>>>(query, key, v_in, inqh, inql, inkh, inkl, invh, invl, n4);
    }
    // (1) weight transposes (fused)
    {
        dim3 g(32, 32, 4), b(32, 8);
        transW_all<<<g, b>>>(Wq, Wk, Wv, Wm, wqh, wql, wkh, wkl, wvh, wvl, wmh, wml);
    }

    // (2-4) Projections — early so ncu's sample window lands on gemm3
    {
        dim3 grid(NHID / 64, (BQ * SEQ) / 128, 1);
        gemm3<0><<<grid, blk, GEMM_SMEM>>>(inqh, inql, RDIM, 0, 0,
                                           wqh, wql, RDIM, 0, 0, bq,
                                           nullptr, qh, ql, NHID, 0, 0,
                                           RDIM, nullptr, 0.f);
        gemm3<0><<<grid, blk, GEMM_SMEM>>>(inkh, inkl, RDIM, 0, 0,
                                           wkh, wkl, RDIM, 0, 0, bk,
                                           nullptr, kh, kl, NHID, 0, 0,
                                           RDIM, nullptr, 0.f);
        gemm3<0><<<grid, blk, GEMM_SMEM>>>(invh, invl, RDIM, 0, 0,
                                           wvh, wvl, RDIM, 0, 0, bv,
                                           nullptr, vh, vl, NHID, 0, 0,
                                           RDIM, nullptr, 0.f);
    }

    // (5) V transpose per batch
    {
        dim3 g(32, 32, BQ), b(32, 8);
        transV<<<g, b>>>(vh, vl, vth, vtl);
    }

    // (6,7) mask canonicalization
    detect_mask_mode<<<1, 256>>>((const unsigned int*)mask);
    convert_mask<<<(BQ * SEQ + 255) / 256, 256>>>(mask, maskp, BQ * SEQ);

    // (8) Scores: per (b,h): M=N=1024, K=128 -> f32 att with scale+mask
    {
        dim3 grid(SEQ / 64, SEQ / 128, BQ * HEADS);
        gemm3<2><<<grid, blk, GEMM_SMEM>>>(qh, ql, NHID, (long long)SEQ * NHID, DKH,
                                           kh, kl, NHID, (long long)SEQ * NHID, DKH,
                                           nullptr,
                                           att_ptr, nullptr, nullptr, SEQ,
                                           (long long)HEADS * SEQ * SEQ, (long long)SEQ * SEQ,
                                           DKH, maskp, scale);
    }

    // (9) Softmax in place (f32 only)
    softmax_rows<<<(unsigned)(BQ * HEADS * SEQ), dim3(128)>>>(att_ptr);

    // (10) PV: f32 att converted in SMEM -> hi/lo atted
    {
        dim3 grid(1, SEQ / 128, BQ * HEADS);
        gemm_pv<<<grid, blk, PV_SMEM>>>(att_ptr, vth, vtl, aedh, aedl);
    }

    // (11) Output projection
    {
        dim3 grid(NHID / 64, (BQ * SEQ) / 128, 1);
        gemm3<1><<<grid, blk, GEMM_SMEM>>>(aedh, aedl, NHID, 0, 0,
                                           wmh, wml, NHID, 0, 0, bm,
                                           atted_ptr, nullptr, nullptr, NHID, 0, 0,
                                           NHID, nullptr, 0.f);
    }
}